// round 11
// baseline (speedup 1.0000x reference)
#include <cuda_runtime.h>
#include <cuda_bf16.h>
#include <stdint.h>

// Problem constants
#define B_   128
#define L_   100
#define F_   900
#define D_   512
#define E_   8

#define BN   128
#define BK   32
#define NKT  29      // ceil(900/32), padded to 928
#define FP   928
#define NROWS (B_ * L_)

// Shared memory layout
#define SM_BM     0
#define SM_STAGES 1024
#define STAGE_BYTES 32768
#define OFF_A_HI  0
#define OFF_A_LO  8192
#define OFF_B_HI  16384
#define OFF_B_LO  24576
#define SMEM_TOTAL (SM_STAGES + 2 * STAGE_BYTES)   // 66560 -> 2 CTAs/SM

// Global scratch
__device__ __nv_bfloat16 g_xhi[(size_t)NROWS * FP];
__device__ __nv_bfloat16 g_xlo[(size_t)NROWS * FP];
__device__ int2   g_topk_idx[B_];
__device__ float2 g_topk_w[B_];

// ---------------- helpers ----------------
__device__ __forceinline__ uint32_t smem_u32(const void* p) {
    uint32_t a;
    asm("{ .reg .u64 t; cvta.to.shared.u64 t, %1; cvt.u32.u64 %0, t; }" : "=r"(a) : "l"(p));
    return a;
}
__device__ __forceinline__ uint32_t swoff(int row, int q) {
    return (uint32_t)(row * 64) + (uint32_t)((q ^ ((row >> 1) & 3)) << 4);
}
__device__ __forceinline__ void cp16(uint32_t dst, const void* src, uint32_t sz) {
    asm volatile("cp.async.cg.shared.global [%0], [%1], 16, %2;"
                 :: "r"(dst), "l"(src), "r"(sz) : "memory");
}
#define CP_COMMIT() asm volatile("cp.async.commit_group;" ::: "memory")
#define CP_WAIT0()  asm volatile("cp.async.wait_group 0;" ::: "memory")

#define LDSM4(r, addr) \
    asm volatile("ldmatrix.sync.aligned.m8n8.x4.shared.b16 {%0,%1,%2,%3}, [%4];" \
        : "=r"((r)[0]), "=r"((r)[1]), "=r"((r)[2]), "=r"((r)[3]) : "r"(addr))
#define LDSM2(r, addr) \
    asm volatile("ldmatrix.sync.aligned.m8n8.x2.shared.b16 {%0,%1}, [%2];" \
        : "=r"((r)[0]), "=r"((r)[1]) : "r"(addr))
#define MMA16816(c, a, bb) \
    asm volatile("mma.sync.aligned.m16n8k16.row.col.f32.bf16.bf16.f32 " \
        "{%0,%1,%2,%3}, {%4,%5,%6,%7}, {%8,%9}, {%0,%1,%2,%3};" \
        : "+f"((c)[0]), "+f"((c)[1]), "+f"((c)[2]), "+f"((c)[3]) \
        : "r"((a)[0]), "r"((a)[1]), "r"((a)[2]), "r"((a)[3]), "r"((bb)[0]), "r"((bb)[1]))

// One MMA sub-step. MI = number of valid M fragments for this warp (3 or 4):
// warp_m==1, mi==3 covers rows 112..127, all padding (L=100) -> skipped.
#define MMA_STEP(sstep, MI) do { \
    const int aq = 2 * (sstep) + ahalf; \
    const int bq = 2 * (sstep) + bhalf; \
    uint32_t aX[4][4]; \
    _Pragma("unroll") \
    for (int mi = 0; mi < 4; mi++) \
        if (mi < (MI)) LDSM4(aX[mi], aHiB + swoff(arow0 + mi * 16, aq)); \
    _Pragma("unroll") \
    for (int nj = 0; nj < 4; nj++) { \
        uint32_t bh[2], bl[2]; \
        uint32_t boff = swoff(brow0 + nj * 8, bq); \
        LDSM2(bh, bHiB + boff); \
        LDSM2(bl, bLoB + boff); \
        _Pragma("unroll") \
        for (int mi = 0; mi < 4; mi++) \
            if (mi < (MI)) { \
                MMA16816(acc[mi][nj], aX[mi], bh); \
                MMA16816(acc[mi][nj], aX[mi], bl); \
            } \
    } \
    _Pragma("unroll") \
    for (int mi = 0; mi < 4; mi++) \
        if (mi < (MI)) LDSM4(aX[mi], aLoB + swoff(arow0 + mi * 16, aq)); \
    _Pragma("unroll") \
    for (int nj = 0; nj < 4; nj++) { \
        uint32_t bh[2]; \
        LDSM2(bh, bHiB + swoff(brow0 + nj * 8, bq)); \
        _Pragma("unroll") \
        for (int mi = 0; mi < 4; mi++) \
            if (mi < (MI)) MMA16816(acc[mi][nj], aX[mi], bh); \
    } \
} while (0)

// ---------------------------------------------------------------------------
// Kernel 0: fused gates + x hi/lo split.
// ---------------------------------------------------------------------------
__global__ void pre_kernel(const float* __restrict__ x,
                           const void* __restrict__ candA,
                           const void* __restrict__ candB) {
    if (blockIdx.x == 0 && threadIdx.x < B_) {
        int b = threadIdx.x;
        const int* ai = (const int*)candA;
        bool aIsMask = true;
#pragma unroll
        for (int e = 0; e < E_; e++) {
            int t = ai[b * E_ + e];
            if (t != 0 && t != 1) aIsMask = false;
        }
        const float* logits = aIsMask ? (const float*)candB : (const float*)candA;
        const int*   masks  = aIsMask ? (const int*)candA   : (const int*)candB;

        float v[E_]; float mx = -1e30f;
#pragma unroll
        for (int e = 0; e < E_; e++) { v[e] = logits[b * E_ + e]; mx = fmaxf(mx, v[e]); }
        float s = 0.f;
#pragma unroll
        for (int e = 0; e < E_; e++) { v[e] = expf(v[e] - mx); s += v[e]; }
        float inv = 1.f / s;
#pragma unroll
        for (int e = 0; e < E_; e++) {
            float m = (masks[b * E_ + e] == 1) ? 1.f : 0.f;
            v[e] = v[e] * inv * m;
        }
        int i1 = 0;
#pragma unroll
        for (int e = 1; e < E_; e++) if (v[e] > v[i1]) i1 = e;
        int i2 = (i1 == 0) ? 1 : 0;
#pragma unroll
        for (int e = 0; e < E_; e++) if (e != i1 && v[e] > v[i2]) i2 = e;
        float g1 = v[i1], g2 = v[i2];
        float invs = 1.f / (g1 + g2 + 1e-9f);
        g_topk_idx[b] = make_int2(i1, i2);
        g_topk_w[b]   = make_float2(g1 * invs, g2 * invs);
    }

    int idx = blockIdx.x * 256 + threadIdx.x;
    if (idx >= NROWS * (FP / 8)) return;
    int row = idx / (FP / 8);
    int c8  = idx % (FP / 8);
    int f   = c8 * 8;
    const float* xr = x + (size_t)row * F_ + f;
    uint32_t hi[4], lo[4];
#pragma unroll
    for (int j = 0; j < 4; j++) {
        float v0 = (f + 2 * j     < F_) ? xr[2 * j]     : 0.f;
        float v1 = (f + 2 * j + 1 < F_) ? xr[2 * j + 1] : 0.f;
        __nv_bfloat16 h0 = __float2bfloat16_rn(v0);
        __nv_bfloat16 h1 = __float2bfloat16_rn(v1);
        __nv_bfloat162 hp; hp.x = h0; hp.y = h1;
        __nv_bfloat162 lp; lp.x = __float2bfloat16_rn(v0 - __bfloat162float(h0));
                           lp.y = __float2bfloat16_rn(v1 - __bfloat162float(h1));
        hi[j] = *(uint32_t*)&hp;
        lo[j] = *(uint32_t*)&lp;
    }
    *(uint4*)(g_xhi + (size_t)row * FP + f) = make_uint4(hi[0], hi[1], hi[2], hi[3]);
    *(uint4*)(g_xlo + (size_t)row * FP + f) = make_uint4(lo[0], lo[1], lo[2], lo[3]);
}

// ---------------------------------------------------------------------------
// Rebalanced producer item mapping:
//   warps 0-3 (full MMA load): 1 item/thread  -> items [0,128)
//   warps 4-7 (reduced MMA):   3 items/thread -> items [128,512)
// ---------------------------------------------------------------------------
__device__ __forceinline__ void issue_A(
    uint32_t stage_u,
    const __nv_bfloat16* __restrict__ xhi_b, const __nv_bfloat16* __restrict__ xlo_b,
    int k0, int tid) {
    const int nIt  = (tid < 128) ? 1 : 3;
    const int base = (tid < 128) ? tid : 128 + (tid - 128) * 3;
#pragma unroll
    for (int ii = 0; ii < 3; ii++) {
        if (ii >= nIt) break;
        int item = base + ii;
        int row = item >> 2, q = item & 3;
        int rc  = (row < L_) ? row : 0;
        uint32_t sz = (row < L_) ? 16u : 0u;
        const __nv_bfloat16* sh = xhi_b + (size_t)rc * FP + k0 + q * 8;
        const __nv_bfloat16* sl = xlo_b + (size_t)rc * FP + k0 + q * 8;
        uint32_t off = swoff(row, q);
        cp16(stage_u + OFF_A_HI + off, sh, sz);
        cp16(stage_u + OFF_A_LO + off, sl, sz);
    }
}

__device__ __forceinline__ void produce_W(
    char* __restrict__ stg,
    const float* __restrict__ W1, const float* __restrict__ W2,
    float gx, float gy, int k0, int tid) {
    const int nIt  = (tid < 128) ? 1 : 3;
    const int base = (tid < 128) ? tid : 128 + (tid - 128) * 3;
#pragma unroll
    for (int ii = 0; ii < 3; ii++) {
        if (ii >= nIt) break;
        int item = base + ii;
        int row  = item >> 2;
        int q    = item & 3;
        int f    = k0 + q * 8;
        float v[8] = {0.f, 0.f, 0.f, 0.f, 0.f, 0.f, 0.f, 0.f};
        if (f + 4 <= F_) {
            float4 a = *(const float4*)(W1 + (size_t)row * F_ + f);
            float4 c = *(const float4*)(W2 + (size_t)row * F_ + f);
            v[0] = fmaf(gx, a.x, gy * c.x); v[1] = fmaf(gx, a.y, gy * c.y);
            v[2] = fmaf(gx, a.z, gy * c.z); v[3] = fmaf(gx, a.w, gy * c.w);
        }
        if (f + 8 <= F_) {
            float4 a = *(const float4*)(W1 + (size_t)row * F_ + f + 4);
            float4 c = *(const float4*)(W2 + (size_t)row * F_ + f + 4);
            v[4] = fmaf(gx, a.x, gy * c.x); v[5] = fmaf(gx, a.y, gy * c.y);
            v[6] = fmaf(gx, a.z, gy * c.z); v[7] = fmaf(gx, a.w, gy * c.w);
        }
        uint32_t hi[4], lo[4];
#pragma unroll
        for (int j = 0; j < 4; j++) {
            __nv_bfloat16 h0 = __float2bfloat16_rn(v[2 * j]);
            __nv_bfloat16 h1 = __float2bfloat16_rn(v[2 * j + 1]);
            __nv_bfloat162 hp; hp.x = h0; hp.y = h1;
            __nv_bfloat162 lp;
            lp.x = __float2bfloat16_rn(v[2 * j]     - __bfloat162float(h0));
            lp.y = __float2bfloat16_rn(v[2 * j + 1] - __bfloat162float(h1));
            hi[j] = *(uint32_t*)&hp;
            lo[j] = *(uint32_t*)&lp;
        }
        uint32_t off = swoff(row, q);
        *(uint4*)(stg + OFF_B_HI + off) = make_uint4(hi[0], hi[1], hi[2], hi[3]);
        *(uint4*)(stg + OFF_B_LO + off) = make_uint4(lo[0], lo[1], lo[2], lo[3]);
    }
}

// ---------------------------------------------------------------------------
// Kernel 2: HMMA 3-pass split GEMM (R9 structure + padded-row MMA skip).
// ---------------------------------------------------------------------------
__global__ void __launch_bounds__(256, 2)
moe_hmma_kernel(const float* __restrict__ W,
                const float* __restrict__ bias,
                float* __restrict__ out) {
    extern __shared__ char smem[];
    const uint32_t sb = smem_u32(smem);
    float* bm = (float*)(smem + SM_BM);

    const int tid    = threadIdx.x;
    const int wid    = tid >> 5;
    const int lane   = tid & 31;
    const int warp_m = wid >> 2;
    const int warp_n = wid & 3;
    const int b      = blockIdx.y;
    const int dtile  = blockIdx.x;

    // warp_m==1 mi==3 covers rows 112-127: pure padding -> skip those MMAs.
    const int MI = (warp_m == 0) ? 4 : 3;

    const int2   ei = g_topk_idx[b];
    const float2 gw = g_topk_w[b];

    const __nv_bfloat16* xhi_b = g_xhi + (size_t)b * L_ * FP;
    const __nv_bfloat16* xlo_b = g_xlo + (size_t)b * L_ * FP;
    const float* __restrict__ W1 = W + (size_t)ei.x * D_ * F_ + (size_t)dtile * BN * F_;
    const float* __restrict__ W2 = W + (size_t)ei.y * D_ * F_ + (size_t)dtile * BN * F_;

    if (tid < BN) {
        int d = dtile * BN + tid;
        bm[tid] = gw.x * bias[ei.x * D_ + d] + gw.y * bias[ei.y * D_ + d];
    }

    float acc[4][4][4];
#pragma unroll
    for (int mi = 0; mi < 4; mi++)
#pragma unroll
        for (int nj = 0; nj < 4; nj++)
#pragma unroll
            for (int q = 0; q < 4; q++) acc[mi][nj][q] = 0.f;

    // prologue: stage 0
    issue_A(sb + SM_STAGES, xhi_b, xlo_b, 0, tid);
    CP_COMMIT();
    produce_W(smem + SM_STAGES, W1, W2, gw.x, gw.y, 0, tid);
    CP_WAIT0();
    __syncthreads();

    const int arow0 = warp_m * 64 + (lane & 15);
    const int ahalf = lane >> 4;
    const int brow0 = warp_n * 32 + (lane & 7);
    const int bhalf = (lane >> 3) & 1;

    for (int t = 0; t < NKT; t++) {
        // prefetch A for t+1; its latency hides behind this tile's MMAs
        if (t + 1 < NKT) {
            issue_A(sb + SM_STAGES + ((t + 1) & 1) * STAGE_BYTES,
                    xhi_b, xlo_b, (t + 1) * BK, tid);
            CP_COMMIT();
        }

        const uint32_t aHiB = sb + SM_STAGES + (t & 1) * STAGE_BYTES + OFF_A_HI;
        const uint32_t aLoB = aHiB + (OFF_A_LO - OFF_A_HI);
        const uint32_t bHiB = aHiB + (OFF_B_HI - OFF_A_HI);
        const uint32_t bLoB = aHiB + (OFF_B_LO - OFF_A_HI);

        MMA_STEP(0, MI);
        MMA_STEP(1, MI);

        if (t + 1 < NKT) {
            produce_W(smem + SM_STAGES + ((t + 1) & 1) * STAGE_BYTES,
                      W1, W2, gw.x, gw.y, (t + 1) * BK, tid);
            CP_WAIT0();
        }
        __syncthreads();
    }

    // ---- epilogue ----
    const int r_base = warp_m * 64 + (lane >> 2);
    const int c_base = warp_n * 32 + ((lane & 3) << 1);
#pragma unroll
    for (int mi = 0; mi < 4; mi++) {
#pragma unroll
        for (int half = 0; half < 2; half++) {
            int l = r_base + mi * 16 + half * 8;
            if (l >= L_) continue;
            float* orow = out + ((size_t)b * L_ + l) * D_ + dtile * BN;
#pragma unroll
            for (int nj = 0; nj < 4; nj++) {
                int c = c_base + nj * 8;
                float v0 = acc[mi][nj][half * 2 + 0] + bm[c];
                float v1 = acc[mi][nj][half * 2 + 1] + bm[c + 1];
                v0 = __bfloat162float(__float2bfloat16_rn(v0));
                v1 = __bfloat162float(__float2bfloat16_rn(v1));
                *(float2*)(orow + c) = make_float2(v0, v1);
            }
        }
    }
}

// ---------------------------------------------------------------------------
extern "C" void kernel_launch(void* const* d_in, const int* in_sizes, int n_in,
                              void* d_out, int out_size) {
    const void* x_p = nullptr;
    const void* W_p = nullptr;
    const void* b_p = nullptr;
    const void* c1024[2] = {nullptr, nullptr};
    int n1024 = 0;

    for (int i = 0; i < n_in; i++) {
        switch (in_sizes[i]) {
            case 11520000: x_p = d_in[i]; break;
            case 3686400:  W_p = d_in[i]; break;
            case 4096:     b_p = d_in[i]; break;
            case 1024: if (n1024 < 2) c1024[n1024++] = d_in[i]; break;
            default: break;
        }
    }
    if (!x_p || !W_p || !b_p || n1024 != 2) {
        x_p = d_in[0]; c1024[0] = d_in[1]; c1024[1] = d_in[2];
        W_p = d_in[3]; b_p = d_in[4];
    }

    float* out = (float*)d_out;

    cudaFuncSetAttribute(moe_hmma_kernel,
                         cudaFuncAttributeMaxDynamicSharedMemorySize, SMEM_TOTAL);

    pre_kernel<<<(NROWS * (FP / 8) + 255) / 256, 256>>>((const float*)x_p,
                                                        c1024[0], c1024[1]);

    dim3 grid(D_ / BN, B_);   // (4, 128)
    moe_hmma_kernel<<<grid, 256, SMEM_TOTAL>>>((const float*)W_p,
                                               (const float*)b_p, out);
}

// round 12
// speedup vs baseline: 1.2667x; 1.2667x over previous
#include <cuda_runtime.h>
#include <cuda_bf16.h>
#include <stdint.h>

// Problem constants
#define B_   128
#define L_   100
#define F_   900
#define D_   512
#define E_   8

#define BN   128
#define BK   32
#define NKT  29      // ceil(900/32), padded to 928
#define FP   928
#define NROWS (B_ * L_)

// Shared memory layout
#define SM_BM     0
#define SM_STAGES 1024
#define STAGE_BYTES 32768
#define OFF_A_HI  0
#define OFF_A_LO  8192
#define OFF_B_HI  16384
#define OFF_B_LO  24576
#define SMEM_TOTAL (SM_STAGES + 2 * STAGE_BYTES)   // 66560 -> 2 CTAs/SM

// Global scratch
__device__ __nv_bfloat16 g_xhi[(size_t)NROWS * FP];
__device__ __nv_bfloat16 g_xlo[(size_t)NROWS * FP];
__device__ int2   g_topk_idx[B_];
__device__ float2 g_topk_w[B_];

// ---------------- helpers ----------------
__device__ __forceinline__ uint32_t smem_u32(const void* p) {
    uint32_t a;
    asm("{ .reg .u64 t; cvta.to.shared.u64 t, %1; cvt.u32.u64 %0, t; }" : "=r"(a) : "l"(p));
    return a;
}
__device__ __forceinline__ uint32_t swoff(int row, int q) {
    return (uint32_t)(row * 64) + (uint32_t)((q ^ ((row >> 1) & 3)) << 4);
}
__device__ __forceinline__ void cp16(uint32_t dst, const void* src, uint32_t sz) {
    asm volatile("cp.async.cg.shared.global [%0], [%1], 16, %2;"
                 :: "r"(dst), "l"(src), "r"(sz) : "memory");
}
#define CP_COMMIT() asm volatile("cp.async.commit_group;" ::: "memory")
#define CP_WAIT0()  asm volatile("cp.async.wait_group 0;" ::: "memory")

#define LDSM4(r, addr) \
    asm volatile("ldmatrix.sync.aligned.m8n8.x4.shared.b16 {%0,%1,%2,%3}, [%4];" \
        : "=r"((r)[0]), "=r"((r)[1]), "=r"((r)[2]), "=r"((r)[3]) : "r"(addr))
#define LDSM2(r, addr) \
    asm volatile("ldmatrix.sync.aligned.m8n8.x2.shared.b16 {%0,%1}, [%2];" \
        : "=r"((r)[0]), "=r"((r)[1]) : "r"(addr))
#define MMA16816(c, a, bb) \
    asm volatile("mma.sync.aligned.m16n8k16.row.col.f32.bf16.bf16.f32 " \
        "{%0,%1,%2,%3}, {%4,%5,%6,%7}, {%8,%9}, {%0,%1,%2,%3};" \
        : "+f"((c)[0]), "+f"((c)[1]), "+f"((c)[2]), "+f"((c)[3]) \
        : "r"((a)[0]), "r"((a)[1]), "r"((a)[2]), "r"((a)[3]), "r"((bb)[0]), "r"((bb)[1]))

// One MMA sub-step. MI = valid M fragments for this warp (4 or 3):
// warp_m==1, mi==3 covers rows 112..127 = pure L-padding -> skipped.
#define MMA_STEP(sstep, MI) do { \
    const int aq = 2 * (sstep) + ahalf; \
    const int bq = 2 * (sstep) + bhalf; \
    uint32_t aX[4][4]; \
    _Pragma("unroll") \
    for (int mi = 0; mi < 4; mi++) \
        if (mi < (MI)) LDSM4(aX[mi], aHiB + swoff(arow0 + mi * 16, aq)); \
    _Pragma("unroll") \
    for (int nj = 0; nj < 4; nj++) { \
        uint32_t bh[2], bl[2]; \
        uint32_t boff = swoff(brow0 + nj * 8, bq); \
        LDSM2(bh, bHiB + boff); \
        LDSM2(bl, bLoB + boff); \
        _Pragma("unroll") \
        for (int mi = 0; mi < 4; mi++) \
            if (mi < (MI)) { \
                MMA16816(acc[mi][nj], aX[mi], bh); \
                MMA16816(acc[mi][nj], aX[mi], bl); \
            } \
    } \
    _Pragma("unroll") \
    for (int mi = 0; mi < 4; mi++) \
        if (mi < (MI)) LDSM4(aX[mi], aLoB + swoff(arow0 + mi * 16, aq)); \
    _Pragma("unroll") \
    for (int nj = 0; nj < 4; nj++) { \
        uint32_t bh[2]; \
        LDSM2(bh, bHiB + swoff(brow0 + nj * 8, bq)); \
        _Pragma("unroll") \
        for (int mi = 0; mi < 4; mi++) \
            if (mi < (MI)) MMA16816(acc[mi][nj], aX[mi], bh); \
    } \
} while (0)

// ---------------------------------------------------------------------------
// Kernel 0: fused gates + x hi/lo split.
// ---------------------------------------------------------------------------
__global__ void pre_kernel(const float* __restrict__ x,
                           const void* __restrict__ candA,
                           const void* __restrict__ candB) {
    if (blockIdx.x == 0 && threadIdx.x < B_) {
        int b = threadIdx.x;
        const int* ai = (const int*)candA;
        bool aIsMask = true;
#pragma unroll
        for (int e = 0; e < E_; e++) {
            int t = ai[b * E_ + e];
            if (t != 0 && t != 1) aIsMask = false;
        }
        const float* logits = aIsMask ? (const float*)candB : (const float*)candA;
        const int*   masks  = aIsMask ? (const int*)candA   : (const int*)candB;

        float v[E_]; float mx = -1e30f;
#pragma unroll
        for (int e = 0; e < E_; e++) { v[e] = logits[b * E_ + e]; mx = fmaxf(mx, v[e]); }
        float s = 0.f;
#pragma unroll
        for (int e = 0; e < E_; e++) { v[e] = expf(v[e] - mx); s += v[e]; }
        float inv = 1.f / s;
#pragma unroll
        for (int e = 0; e < E_; e++) {
            float m = (masks[b * E_ + e] == 1) ? 1.f : 0.f;
            v[e] = v[e] * inv * m;
        }
        int i1 = 0;
#pragma unroll
        for (int e = 1; e < E_; e++) if (v[e] > v[i1]) i1 = e;
        int i2 = (i1 == 0) ? 1 : 0;
#pragma unroll
        for (int e = 0; e < E_; e++) if (e != i1 && v[e] > v[i2]) i2 = e;
        float g1 = v[i1], g2 = v[i2];
        float invs = 1.f / (g1 + g2 + 1e-9f);
        g_topk_idx[b] = make_int2(i1, i2);
        g_topk_w[b]   = make_float2(g1 * invs, g2 * invs);
    }

    int idx = blockIdx.x * 256 + threadIdx.x;
    if (idx >= NROWS * (FP / 8)) return;
    int row = idx / (FP / 8);
    int c8  = idx % (FP / 8);
    int f   = c8 * 8;
    const float* xr = x + (size_t)row * F_ + f;
    uint32_t hi[4], lo[4];
#pragma unroll
    for (int j = 0; j < 4; j++) {
        float v0 = (f + 2 * j     < F_) ? xr[2 * j]     : 0.f;
        float v1 = (f + 2 * j + 1 < F_) ? xr[2 * j + 1] : 0.f;
        __nv_bfloat16 h0 = __float2bfloat16_rn(v0);
        __nv_bfloat16 h1 = __float2bfloat16_rn(v1);
        __nv_bfloat162 hp; hp.x = h0; hp.y = h1;
        __nv_bfloat162 lp; lp.x = __float2bfloat16_rn(v0 - __bfloat162float(h0));
                           lp.y = __float2bfloat16_rn(v1 - __bfloat162float(h1));
        hi[j] = *(uint32_t*)&hp;
        lo[j] = *(uint32_t*)&lp;
    }
    *(uint4*)(g_xhi + (size_t)row * FP + f) = make_uint4(hi[0], hi[1], hi[2], hi[3]);
    *(uint4*)(g_xlo + (size_t)row * FP + f) = make_uint4(lo[0], lo[1], lo[2], lo[3]);
}

// ---------------------------------------------------------------------------
// A prefetch (R9 mapping: item = tid + it*256, coalesced).
// ---------------------------------------------------------------------------
__device__ __forceinline__ void issue_A(
    uint32_t stage_u,
    const __nv_bfloat16* __restrict__ xhi_b, const __nv_bfloat16* __restrict__ xlo_b,
    int k0, int tid) {
#pragma unroll
    for (int it = 0; it < 2; it++) {
        int i   = tid + it * 256;
        int row = i >> 2, q = i & 3;
        int rc  = (row < L_) ? row : 0;
        uint32_t sz = (row < L_) ? 16u : 0u;
        const __nv_bfloat16* sh = xhi_b + (size_t)rc * FP + k0 + q * 8;
        const __nv_bfloat16* sl = xlo_b + (size_t)rc * FP + k0 + q * 8;
        uint32_t off = swoff(row, q);
        cp16(stage_u + OFF_A_HI + off, sh, sz);
        cp16(stage_u + OFF_A_LO + off, sl, sz);
    }
}

// ---------------------------------------------------------------------------
// W producer (R9 mapping, coalesced): direct LDG fp32, gate-mix, split, STS.
// ---------------------------------------------------------------------------
__device__ __forceinline__ void produce_W(
    char* __restrict__ stg,
    const float* __restrict__ W1, const float* __restrict__ W2,
    float gx, float gy, int k0, int tid) {
#pragma unroll
    for (int it = 0; it < 2; it++) {
        int item = tid + it * 256;
        int row  = item >> 2;
        int q    = item & 3;
        int f    = k0 + q * 8;
        float v[8] = {0.f, 0.f, 0.f, 0.f, 0.f, 0.f, 0.f, 0.f};
        if (f + 4 <= F_) {
            float4 a = *(const float4*)(W1 + (size_t)row * F_ + f);
            float4 c = *(const float4*)(W2 + (size_t)row * F_ + f);
            v[0] = fmaf(gx, a.x, gy * c.x); v[1] = fmaf(gx, a.y, gy * c.y);
            v[2] = fmaf(gx, a.z, gy * c.z); v[3] = fmaf(gx, a.w, gy * c.w);
        }
        if (f + 8 <= F_) {
            float4 a = *(const float4*)(W1 + (size_t)row * F_ + f + 4);
            float4 c = *(const float4*)(W2 + (size_t)row * F_ + f + 4);
            v[4] = fmaf(gx, a.x, gy * c.x); v[5] = fmaf(gx, a.y, gy * c.y);
            v[6] = fmaf(gx, a.z, gy * c.z); v[7] = fmaf(gx, a.w, gy * c.w);
        }
        uint32_t hi[4], lo[4];
#pragma unroll
        for (int j = 0; j < 4; j++) {
            __nv_bfloat16 h0 = __float2bfloat16_rn(v[2 * j]);
            __nv_bfloat16 h1 = __float2bfloat16_rn(v[2 * j + 1]);
            __nv_bfloat162 hp; hp.x = h0; hp.y = h1;
            __nv_bfloat162 lp;
            lp.x = __float2bfloat16_rn(v[2 * j]     - __bfloat162float(h0));
            lp.y = __float2bfloat16_rn(v[2 * j + 1] - __bfloat162float(h1));
            hi[j] = *(uint32_t*)&hp;
            lo[j] = *(uint32_t*)&lp;
        }
        uint32_t off = swoff(row, q);
        *(uint4*)(stg + OFF_B_HI + off) = make_uint4(hi[0], hi[1], hi[2], hi[3]);
        *(uint4*)(stg + OFF_B_LO + off) = make_uint4(lo[0], lo[1], lo[2], lo[3]);
    }
}

// ---------------------------------------------------------------------------
// Kernel 2: HMMA 3-pass split GEMM = R9 + padded-row MMA skip (only change).
// ---------------------------------------------------------------------------
__global__ void __launch_bounds__(256, 2)
moe_hmma_kernel(const float* __restrict__ W,
                const float* __restrict__ bias,
                float* __restrict__ out) {
    extern __shared__ char smem[];
    const uint32_t sb = smem_u32(smem);
    float* bm = (float*)(smem + SM_BM);

    const int tid    = threadIdx.x;
    const int wid    = tid >> 5;
    const int lane   = tid & 31;
    const int warp_m = wid >> 2;
    const int warp_n = wid & 3;
    const int b      = blockIdx.y;
    const int dtile  = blockIdx.x;

    // warp_m==1 mi==3 covers rows 112-127: pure padding -> skip those MMAs.
    const int MI = (warp_m == 0) ? 4 : 3;

    const int2   ei = g_topk_idx[b];
    const float2 gw = g_topk_w[b];

    const __nv_bfloat16* xhi_b = g_xhi + (size_t)b * L_ * FP;
    const __nv_bfloat16* xlo_b = g_xlo + (size_t)b * L_ * FP;
    const float* __restrict__ W1 = W + (size_t)ei.x * D_ * F_ + (size_t)dtile * BN * F_;
    const float* __restrict__ W2 = W + (size_t)ei.y * D_ * F_ + (size_t)dtile * BN * F_;

    if (tid < BN) {
        int d = dtile * BN + tid;
        bm[tid] = gw.x * bias[ei.x * D_ + d] + gw.y * bias[ei.y * D_ + d];
    }

    float acc[4][4][4];
#pragma unroll
    for (int mi = 0; mi < 4; mi++)
#pragma unroll
        for (int nj = 0; nj < 4; nj++)
#pragma unroll
            for (int q = 0; q < 4; q++) acc[mi][nj][q] = 0.f;

    // prologue: stage 0
    issue_A(sb + SM_STAGES, xhi_b, xlo_b, 0, tid);
    CP_COMMIT();
    produce_W(smem + SM_STAGES, W1, W2, gw.x, gw.y, 0, tid);
    CP_WAIT0();
    __syncthreads();

    const int arow0 = warp_m * 64 + (lane & 15);
    const int ahalf = lane >> 4;
    const int brow0 = warp_n * 32 + (lane & 7);
    const int bhalf = (lane >> 3) & 1;

    for (int t = 0; t < NKT; t++) {
        // prefetch A for t+1; latency hides behind this tile's MMAs
        if (t + 1 < NKT) {
            issue_A(sb + SM_STAGES + ((t + 1) & 1) * STAGE_BYTES,
                    xhi_b, xlo_b, (t + 1) * BK, tid);
            CP_COMMIT();
        }

        const uint32_t aHiB = sb + SM_STAGES + (t & 1) * STAGE_BYTES + OFF_A_HI;
        const uint32_t aLoB = aHiB + (OFF_A_LO - OFF_A_HI);
        const uint32_t bHiB = aHiB + (OFF_B_HI - OFF_A_HI);
        const uint32_t bLoB = aHiB + (OFF_B_LO - OFF_A_HI);

        MMA_STEP(0, MI);
        MMA_STEP(1, MI);

        if (t + 1 < NKT) {
            produce_W(smem + SM_STAGES + ((t + 1) & 1) * STAGE_BYTES,
                      W1, W2, gw.x, gw.y, (t + 1) * BK, tid);
            CP_WAIT0();
        }
        __syncthreads();
    }

    // ---- epilogue ----
    const int r_base = warp_m * 64 + (lane >> 2);
    const int c_base = warp_n * 32 + ((lane & 3) << 1);
#pragma unroll
    for (int mi = 0; mi < 4; mi++) {
#pragma unroll
        for (int half = 0; half < 2; half++) {
            int l = r_base + mi * 16 + half * 8;
            if (l >= L_) continue;
            float* orow = out + ((size_t)b * L_ + l) * D_ + dtile * BN;
#pragma unroll
            for (int nj = 0; nj < 4; nj++) {
                int c = c_base + nj * 8;
                float v0 = acc[mi][nj][half * 2 + 0] + bm[c];
                float v1 = acc[mi][nj][half * 2 + 1] + bm[c + 1];
                v0 = __bfloat162float(__float2bfloat16_rn(v0));
                v1 = __bfloat162float(__float2bfloat16_rn(v1));
                *(float2*)(orow + c) = make_float2(v0, v1);
            }
        }
    }
}

// ---------------------------------------------------------------------------
extern "C" void kernel_launch(void* const* d_in, const int* in_sizes, int n_in,
                              void* d_out, int out_size) {
    const void* x_p = nullptr;
    const void* W_p = nullptr;
    const void* b_p = nullptr;
    const void* c1024[2] = {nullptr, nullptr};
    int n1024 = 0;

    for (int i = 0; i < n_in; i++) {
        switch (in_sizes[i]) {
            case 11520000: x_p = d_in[i]; break;
            case 3686400:  W_p = d_in[i]; break;
            case 4096:     b_p = d_in[i]; break;
            case 1024: if (n1024 < 2) c1024[n1024++] = d_in[i]; break;
            default: break;
        }
    }
    if (!x_p || !W_p || !b_p || n1024 != 2) {
        x_p = d_in[0]; c1024[0] = d_in[1]; c1024[1] = d_in[2];
        W_p = d_in[3]; b_p = d_in[4];
    }

    float* out = (float*)d_out;

    cudaFuncSetAttribute(moe_hmma_kernel,
                         cudaFuncAttributeMaxDynamicSharedMemorySize, SMEM_TOTAL);

    pre_kernel<<<(NROWS * (FP / 8) + 255) / 256, 256>>>((const float*)x_p,
                                                        c1024[0], c1024[1]);

    dim3 grid(D_ / BN, B_);   // (4, 128)
    moe_hmma_kernel<<<grid, 256, SMEM_TOTAL>>>((const float*)W_p,
                                               (const float*)b_p, out);
}

// round 13
// speedup vs baseline: 1.3293x; 1.0494x over previous
#include <cuda_runtime.h>
#include <cuda_bf16.h>
#include <stdint.h>

// Problem constants
#define B_   128
#define L_   100
#define F_   900
#define D_   512
#define E_   8

#define BN   128
#define BK   32
#define NKT  29      // ceil(900/32), padded to 928
#define FP   928
#define NROWS (B_ * L_)

// Shared memory layout
#define SM_BM     0
#define SM_STAGES 1024
#define STAGE_BYTES 32768
#define OFF_A_HI  0
#define OFF_A_LO  8192
#define OFF_B_HI  16384
#define OFF_B_LO  24576
#define SMEM_TOTAL (SM_STAGES + 2 * STAGE_BYTES)   // 66560 -> 2 CTAs/SM

// Global scratch
__device__ __nv_bfloat16 g_xhi[(size_t)NROWS * FP];
__device__ __nv_bfloat16 g_xlo[(size_t)NROWS * FP];
__device__ int2   g_topk_idx[B_];
__device__ float2 g_topk_w[B_];

// ---------------- helpers ----------------
__device__ __forceinline__ uint32_t smem_u32(const void* p) {
    uint32_t a;
    asm("{ .reg .u64 t; cvta.to.shared.u64 t, %1; cvt.u32.u64 %0, t; }" : "=r"(a) : "l"(p));
    return a;
}
__device__ __forceinline__ uint32_t swoff(int row, int q) {
    return (uint32_t)(row * 64) + (uint32_t)((q ^ ((row >> 1) & 3)) << 4);
}
__device__ __forceinline__ void cp16(uint32_t dst, const void* src, uint32_t sz) {
    asm volatile("cp.async.cg.shared.global [%0], [%1], 16, %2;"
                 :: "r"(dst), "l"(src), "r"(sz) : "memory");
}
#define CP_COMMIT() asm volatile("cp.async.commit_group;" ::: "memory")
#define CP_WAIT0()  asm volatile("cp.async.wait_group 0;" ::: "memory")

#define LDSM4(r, addr) \
    asm volatile("ldmatrix.sync.aligned.m8n8.x4.shared.b16 {%0,%1,%2,%3}, [%4];" \
        : "=r"((r)[0]), "=r"((r)[1]), "=r"((r)[2]), "=r"((r)[3]) : "r"(addr))
#define LDSM2(r, addr) \
    asm volatile("ldmatrix.sync.aligned.m8n8.x2.shared.b16 {%0,%1}, [%2];" \
        : "=r"((r)[0]), "=r"((r)[1]) : "r"(addr))
#define MMA16816(c, a, bb) \
    asm volatile("mma.sync.aligned.m16n8k16.row.col.f32.bf16.bf16.f32 " \
        "{%0,%1,%2,%3}, {%4,%5,%6,%7}, {%8,%9}, {%0,%1,%2,%3};" \
        : "+f"((c)[0]), "+f"((c)[1]), "+f"((c)[2]), "+f"((c)[3]) \
        : "r"((a)[0]), "r"((a)[1]), "r"((a)[2]), "r"((a)[3]), "r"((bb)[0]), "r"((bb)[1]))

// Fast bf16 hi/lo split for a pair: bit-identical to per-element rn split.
// hp = [bf16(v1) | bf16(v0)], lp likewise for the residuals.
__device__ __forceinline__ void split2(float v0, float v1, uint32_t& hp, uint32_t& lp) {
    asm("cvt.rn.bf16x2.f32 %0, %1, %2;" : "=r"(hp) : "f"(v1), "f"(v0));
    float f0h = __uint_as_float(hp << 16);          // float(bf16(v0))
    float f1h = __uint_as_float(hp & 0xFFFF0000u);  // float(bf16(v1))
    float l0 = v0 - f0h;                            // exact (Sterbenz)
    float l1 = v1 - f1h;
    asm("cvt.rn.bf16x2.f32 %0, %1, %2;" : "=r"(lp) : "f"(l1), "f"(l0));
}

// ---------------------------------------------------------------------------
// Kernel 0a: gates (self-disambiguates logits vs masks by bit pattern)
// ---------------------------------------------------------------------------
__global__ void gates_kernel(const void* __restrict__ candA,
                             const void* __restrict__ candB) {
    int b = threadIdx.x;
    if (b >= B_) return;
    const int* ai = (const int*)candA;
    bool aIsMask = true;
#pragma unroll
    for (int e = 0; e < E_; e++) {
        int t = ai[b * E_ + e];
        if (t != 0 && t != 1) aIsMask = false;
    }
    const float* logits = aIsMask ? (const float*)candB : (const float*)candA;
    const int*   masks  = aIsMask ? (const int*)candA   : (const int*)candB;

    float v[E_]; float mx = -1e30f;
#pragma unroll
    for (int e = 0; e < E_; e++) { v[e] = logits[b * E_ + e]; mx = fmaxf(mx, v[e]); }
    float s = 0.f;
#pragma unroll
    for (int e = 0; e < E_; e++) { v[e] = expf(v[e] - mx); s += v[e]; }
    float inv = 1.f / s;
#pragma unroll
    for (int e = 0; e < E_; e++) {
        float m = (masks[b * E_ + e] == 1) ? 1.f : 0.f;
        v[e] = v[e] * inv * m;
    }
    int i1 = 0;
#pragma unroll
    for (int e = 1; e < E_; e++) if (v[e] > v[i1]) i1 = e;
    int i2 = (i1 == 0) ? 1 : 0;
#pragma unroll
    for (int e = 0; e < E_; e++) if (e != i1 && v[e] > v[i2]) i2 = e;
    float g1 = v[i1], g2 = v[i2];
    float invs = 1.f / (g1 + g2 + 1e-9f);
    g_topk_idx[b] = make_int2(i1, i2);
    g_topk_w[b]   = make_float2(g1 * invs, g2 * invs);
}

// ---------------------------------------------------------------------------
// Kernel 0b: split x into bf16 hi/lo, zero-padded cols to FP=928
// ---------------------------------------------------------------------------
__global__ void split_x_kernel(const float* __restrict__ x) {
    int idx = blockIdx.x * 256 + threadIdx.x;
    if (idx >= NROWS * (FP / 8)) return;
    int row = idx / (FP / 8);
    int c8  = idx % (FP / 8);
    int f   = c8 * 8;
    const float* xr = x + (size_t)row * F_ + f;
    uint32_t hi[4], lo[4];
#pragma unroll
    for (int j = 0; j < 4; j++) {
        float v0 = (f + 2 * j     < F_) ? xr[2 * j]     : 0.f;
        float v1 = (f + 2 * j + 1 < F_) ? xr[2 * j + 1] : 0.f;
        split2(v0, v1, hi[j], lo[j]);
    }
    *(uint4*)(g_xhi + (size_t)row * FP + f) = make_uint4(hi[0], hi[1], hi[2], hi[3]);
    *(uint4*)(g_xlo + (size_t)row * FP + f) = make_uint4(lo[0], lo[1], lo[2], lo[3]);
}

// ---------------------------------------------------------------------------
// A prefetch (coalesced: item = tid + it*256).
// ---------------------------------------------------------------------------
__device__ __forceinline__ void issue_A(
    uint32_t stage_u,
    const __nv_bfloat16* __restrict__ xhi_b, const __nv_bfloat16* __restrict__ xlo_b,
    int k0, int tid) {
#pragma unroll
    for (int it = 0; it < 2; it++) {
        int i   = tid + it * 256;
        int row = i >> 2, q = i & 3;
        int rc  = (row < L_) ? row : 0;
        uint32_t sz = (row < L_) ? 16u : 0u;
        const __nv_bfloat16* sh = xhi_b + (size_t)rc * FP + k0 + q * 8;
        const __nv_bfloat16* sl = xlo_b + (size_t)rc * FP + k0 + q * 8;
        uint32_t off = swoff(row, q);
        cp16(stage_u + OFF_A_HI + off, sh, sz);
        cp16(stage_u + OFF_A_LO + off, sl, sz);
    }
}

// ---------------------------------------------------------------------------
// W producer (coalesced): direct LDG fp32, gate-mix, fast split, STS.
// ---------------------------------------------------------------------------
__device__ __forceinline__ void produce_W(
    char* __restrict__ stg,
    const float* __restrict__ W1, const float* __restrict__ W2,
    float gx, float gy, int k0, int tid) {
#pragma unroll
    for (int it = 0; it < 2; it++) {
        int item = tid + it * 256;
        int row  = item >> 2;
        int q    = item & 3;
        int f    = k0 + q * 8;
        float v[8] = {0.f, 0.f, 0.f, 0.f, 0.f, 0.f, 0.f, 0.f};
        if (f + 4 <= F_) {
            float4 a = *(const float4*)(W1 + (size_t)row * F_ + f);
            float4 c = *(const float4*)(W2 + (size_t)row * F_ + f);
            v[0] = fmaf(gx, a.x, gy * c.x); v[1] = fmaf(gx, a.y, gy * c.y);
            v[2] = fmaf(gx, a.z, gy * c.z); v[3] = fmaf(gx, a.w, gy * c.w);
        }
        if (f + 8 <= F_) {
            float4 a = *(const float4*)(W1 + (size_t)row * F_ + f + 4);
            float4 c = *(const float4*)(W2 + (size_t)row * F_ + f + 4);
            v[4] = fmaf(gx, a.x, gy * c.x); v[5] = fmaf(gx, a.y, gy * c.y);
            v[6] = fmaf(gx, a.z, gy * c.z); v[7] = fmaf(gx, a.w, gy * c.w);
        }
        uint32_t hi[4], lo[4];
#pragma unroll
        for (int j = 0; j < 4; j++)
            split2(v[2 * j], v[2 * j + 1], hi[j], lo[j]);
        uint32_t off = swoff(row, q);
        *(uint4*)(stg + OFF_B_HI + off) = make_uint4(hi[0], hi[1], hi[2], hi[3]);
        *(uint4*)(stg + OFF_B_LO + off) = make_uint4(lo[0], lo[1], lo[2], lo[3]);
    }
}

// ---------------------------------------------------------------------------
// Kernel 2: HMMA bf16 3-pass split GEMM (exact R9 structure).
// ---------------------------------------------------------------------------
__global__ void __launch_bounds__(256, 2)
moe_hmma_kernel(const float* __restrict__ W,
                const float* __restrict__ bias,
                float* __restrict__ out) {
    extern __shared__ char smem[];
    const uint32_t sb = smem_u32(smem);
    float* bm = (float*)(smem + SM_BM);

    const int tid    = threadIdx.x;
    const int wid    = tid >> 5;
    const int lane   = tid & 31;
    const int warp_m = wid >> 2;
    const int warp_n = wid & 3;
    const int b      = blockIdx.y;
    const int dtile  = blockIdx.x;

    const int2   ei = g_topk_idx[b];
    const float2 gw = g_topk_w[b];

    const __nv_bfloat16* xhi_b = g_xhi + (size_t)b * L_ * FP;
    const __nv_bfloat16* xlo_b = g_xlo + (size_t)b * L_ * FP;
    const float* __restrict__ W1 = W + (size_t)ei.x * D_ * F_ + (size_t)dtile * BN * F_;
    const float* __restrict__ W2 = W + (size_t)ei.y * D_ * F_ + (size_t)dtile * BN * F_;

    if (tid < BN) {
        int d = dtile * BN + tid;
        bm[tid] = gw.x * bias[ei.x * D_ + d] + gw.y * bias[ei.y * D_ + d];
    }

    float acc[4][4][4];
#pragma unroll
    for (int mi = 0; mi < 4; mi++)
#pragma unroll
        for (int nj = 0; nj < 4; nj++)
#pragma unroll
            for (int q = 0; q < 4; q++) acc[mi][nj][q] = 0.f;

    // prologue: stage 0
    issue_A(sb + SM_STAGES, xhi_b, xlo_b, 0, tid);
    CP_COMMIT();
    produce_W(smem + SM_STAGES, W1, W2, gw.x, gw.y, 0, tid);
    CP_WAIT0();
    __syncthreads();

    const int arow0 = warp_m * 64 + (lane & 15);
    const int ahalf = lane >> 4;
    const int brow0 = warp_n * 32 + (lane & 7);
    const int bhalf = (lane >> 3) & 1;

    for (int t = 0; t < NKT; t++) {
        if (t + 1 < NKT) {
            issue_A(sb + SM_STAGES + ((t + 1) & 1) * STAGE_BYTES,
                    xhi_b, xlo_b, (t + 1) * BK, tid);
            CP_COMMIT();
        }

        const uint32_t aHiB = sb + SM_STAGES + (t & 1) * STAGE_BYTES + OFF_A_HI;
        const uint32_t aLoB = aHiB + (OFF_A_LO - OFF_A_HI);
        const uint32_t bHiB = aHiB + (OFF_B_HI - OFF_A_HI);
        const uint32_t bLoB = aHiB + (OFF_B_LO - OFF_A_HI);

#pragma unroll
        for (int s = 0; s < 2; s++) {
            const int aq = 2 * s + ahalf;
            const int bq = 2 * s + bhalf;
            uint32_t aX[4][4];

            // pass A-hi: hi*hi + hi*lo
#pragma unroll
            for (int mi = 0; mi < 4; mi++)
                LDSM4(aX[mi], aHiB + swoff(arow0 + mi * 16, aq));
#pragma unroll
            for (int nj = 0; nj < 4; nj++) {
                uint32_t bh[2], bl[2];
                uint32_t boff = swoff(brow0 + nj * 8, bq);
                LDSM2(bh, bHiB + boff);
                LDSM2(bl, bLoB + boff);
#pragma unroll
                for (int mi = 0; mi < 4; mi++) {
                    MMA16816(acc[mi][nj], aX[mi], bh);
                    MMA16816(acc[mi][nj], aX[mi], bl);
                }
            }
            // pass A-lo: lo*hi
#pragma unroll
            for (int mi = 0; mi < 4; mi++)
                LDSM4(aX[mi], aLoB + swoff(arow0 + mi * 16, aq));
#pragma unroll
            for (int nj = 0; nj < 4; nj++) {
                uint32_t bh[2];
                LDSM2(bh, bHiB + swoff(brow0 + nj * 8, bq));
#pragma unroll
                for (int mi = 0; mi < 4; mi++)
                    MMA16816(acc[mi][nj], aX[mi], bh);
            }
        }

        if (t + 1 < NKT) {
            produce_W(smem + SM_STAGES + ((t + 1) & 1) * STAGE_BYTES,
                      W1, W2, gw.x, gw.y, (t + 1) * BK, tid);
            CP_WAIT0();
        }
        __syncthreads();
    }

    // ---- epilogue ----
    const int r_base = warp_m * 64 + (lane >> 2);
    const int c_base = warp_n * 32 + ((lane & 3) << 1);
#pragma unroll
    for (int mi = 0; mi < 4; mi++) {
#pragma unroll
        for (int half = 0; half < 2; half++) {
            int l = r_base + mi * 16 + half * 8;
            if (l >= L_) continue;
            float* orow = out + ((size_t)b * L_ + l) * D_ + dtile * BN;
#pragma unroll
            for (int nj = 0; nj < 4; nj++) {
                int c = c_base + nj * 8;
                float v0 = acc[mi][nj][half * 2 + 0] + bm[c];
                float v1 = acc[mi][nj][half * 2 + 1] + bm[c + 1];
                v0 = __bfloat162float(__float2bfloat16_rn(v0));
                v1 = __bfloat162float(__float2bfloat16_rn(v1));
                *(float2*)(orow + c) = make_float2(v0, v1);
            }
        }
    }
}

// ---------------------------------------------------------------------------
extern "C" void kernel_launch(void* const* d_in, const int* in_sizes, int n_in,
                              void* d_out, int out_size) {
    const void* x_p = nullptr;
    const void* W_p = nullptr;
    const void* b_p = nullptr;
    const void* c1024[2] = {nullptr, nullptr};
    int n1024 = 0;

    for (int i = 0; i < n_in; i++) {
        switch (in_sizes[i]) {
            case 11520000: x_p = d_in[i]; break;
            case 3686400:  W_p = d_in[i]; break;
            case 4096:     b_p = d_in[i]; break;
            case 1024: if (n1024 < 2) c1024[n1024++] = d_in[i]; break;
            default: break;
        }
    }
    if (!x_p || !W_p || !b_p || n1024 != 2) {
        x_p = d_in[0]; c1024[0] = d_in[1]; c1024[1] = d_in[2];
        W_p = d_in[3]; b_p = d_in[4];
    }

    float* out = (float*)d_out;

    cudaFuncSetAttribute(moe_hmma_kernel,
                         cudaFuncAttributeMaxDynamicSharedMemorySize, SMEM_TOTAL);

    gates_kernel<<<1, B_>>>(c1024[0], c1024[1]);
    split_x_kernel<<<(NROWS * (FP / 8) + 255) / 256, 256>>>((const float*)x_p);

    dim3 grid(D_ / BN, B_);   // (4, 128)
    moe_hmma_kernel<<<grid, 256, SMEM_TOTAL>>>((const float*)W_p,
                                               (const float*)b_p, out);
}

// round 14
// speedup vs baseline: 1.3675x; 1.0287x over previous
#include <cuda_runtime.h>
#include <cuda_bf16.h>
#include <stdint.h>

// Problem constants
#define B_   128
#define L_   100
#define F_   900
#define D_   512
#define E_   8

#define BN   128
#define BK   32
#define NKT  29      // ceil(900/32), padded to 928
#define FP   928
#define NROWS (B_ * L_)

// Shared memory layout
#define SM_BM     0
#define SM_STAGES 1024
#define STAGE_BYTES 32768
#define OFF_A_HI  0
#define OFF_A_LO  8192
#define OFF_B_HI  16384
#define OFF_B_LO  24576
#define SMEM_TOTAL (SM_STAGES + 2 * STAGE_BYTES)   // 66560 -> 2 CTAs/SM

// Global scratch
__device__ __nv_bfloat16 g_xhi[(size_t)NROWS * FP];
__device__ __nv_bfloat16 g_xlo[(size_t)NROWS * FP];
__device__ int2   g_topk_idx[B_];
__device__ float2 g_topk_w[B_];

// ---------------- helpers ----------------
__device__ __forceinline__ uint32_t smem_u32(const void* p) {
    uint32_t a;
    asm("{ .reg .u64 t; cvta.to.shared.u64 t, %1; cvt.u32.u64 %0, t; }" : "=r"(a) : "l"(p));
    return a;
}
__device__ __forceinline__ uint32_t swoff(int row, int q) {
    return (uint32_t)(row * 64) + (uint32_t)((q ^ ((row >> 1) & 3)) << 4);
}
__device__ __forceinline__ void cp16(uint32_t dst, const void* src, uint32_t sz) {
    asm volatile("cp.async.cg.shared.global [%0], [%1], 16, %2;"
                 :: "r"(dst), "l"(src), "r"(sz) : "memory");
}
#define CP_COMMIT() asm volatile("cp.async.commit_group;" ::: "memory")
#define CP_WAIT0()  asm volatile("cp.async.wait_group 0;" ::: "memory")

#define LDSM4(r, addr) \
    asm volatile("ldmatrix.sync.aligned.m8n8.x4.shared.b16 {%0,%1,%2,%3}, [%4];" \
        : "=r"((r)[0]), "=r"((r)[1]), "=r"((r)[2]), "=r"((r)[3]) : "r"(addr))
#define LDSM2(r, addr) \
    asm volatile("ldmatrix.sync.aligned.m8n8.x2.shared.b16 {%0,%1}, [%2];" \
        : "=r"((r)[0]), "=r"((r)[1]) : "r"(addr))
#define MMA16816(c, a, bb) \
    asm volatile("mma.sync.aligned.m16n8k16.row.col.f32.bf16.bf16.f32 " \
        "{%0,%1,%2,%3}, {%4,%5,%6,%7}, {%8,%9}, {%0,%1,%2,%3};" \
        : "+f"((c)[0]), "+f"((c)[1]), "+f"((c)[2]), "+f"((c)[3]) \
        : "r"((a)[0]), "r"((a)[1]), "r"((a)[2]), "r"((a)[3]), "r"((bb)[0]), "r"((bb)[1]))

// Fast bf16 hi/lo split: bit-identical to per-element rn split.
__device__ __forceinline__ void split2(float v0, float v1, uint32_t& hp, uint32_t& lp) {
    asm("cvt.rn.bf16x2.f32 %0, %1, %2;" : "=r"(hp) : "f"(v1), "f"(v0));
    float f0h = __uint_as_float(hp << 16);
    float f1h = __uint_as_float(hp & 0xFFFF0000u);
    float l0 = v0 - f0h;
    float l1 = v1 - f1h;
    asm("cvt.rn.bf16x2.f32 %0, %1, %2;" : "=r"(lp) : "f"(l1), "f"(l0));
}

// ---------------------------------------------------------------------------
// Templated per-ktile MMA body: MI = valid M fragments (4 for warp_m 0,
// 3 for warp_m 1 -- its mi==3 covers rows 112..127, pure L-padding).
// Fully unrolled, constant trip counts, no predication.
// ---------------------------------------------------------------------------
template<int MI>
__device__ __forceinline__ void mma_steps(
    float (&acc)[4][4][4],
    uint32_t aHiB, uint32_t aLoB, uint32_t bHiB, uint32_t bLoB,
    int arow0, int ahalf, int brow0, int bhalf) {
#pragma unroll
    for (int s = 0; s < 2; s++) {
        const int aq = 2 * s + ahalf;
        const int bq = 2 * s + bhalf;
        uint32_t aX[MI][4];

        // pass A-hi: hi*hi + hi*lo
#pragma unroll
        for (int mi = 0; mi < MI; mi++)
            LDSM4(aX[mi], aHiB + swoff(arow0 + mi * 16, aq));
#pragma unroll
        for (int nj = 0; nj < 4; nj++) {
            uint32_t bh[2], bl[2];
            uint32_t boff = swoff(brow0 + nj * 8, bq);
            LDSM2(bh, bHiB + boff);
            LDSM2(bl, bLoB + boff);
#pragma unroll
            for (int mi = 0; mi < MI; mi++) {
                MMA16816(acc[mi][nj], aX[mi], bh);
                MMA16816(acc[mi][nj], aX[mi], bl);
            }
        }
        // pass A-lo: lo*hi
#pragma unroll
        for (int mi = 0; mi < MI; mi++)
            LDSM4(aX[mi], aLoB + swoff(arow0 + mi * 16, aq));
#pragma unroll
        for (int nj = 0; nj < 4; nj++) {
            uint32_t bh[2];
            LDSM2(bh, bHiB + swoff(brow0 + nj * 8, bq));
#pragma unroll
            for (int mi = 0; mi < MI; mi++)
                MMA16816(acc[mi][nj], aX[mi], bh);
        }
    }
}

// ---------------------------------------------------------------------------
// Kernel 0a: gates (self-disambiguates logits vs masks by bit pattern)
// ---------------------------------------------------------------------------
__global__ void gates_kernel(const void* __restrict__ candA,
                             const void* __restrict__ candB) {
    int b = threadIdx.x;
    if (b >= B_) return;
    const int* ai = (const int*)candA;
    bool aIsMask = true;
#pragma unroll
    for (int e = 0; e < E_; e++) {
        int t = ai[b * E_ + e];
        if (t != 0 && t != 1) aIsMask = false;
    }
    const float* logits = aIsMask ? (const float*)candB : (const float*)candA;
    const int*   masks  = aIsMask ? (const int*)candA   : (const int*)candB;

    float v[E_]; float mx = -1e30f;
#pragma unroll
    for (int e = 0; e < E_; e++) { v[e] = logits[b * E_ + e]; mx = fmaxf(mx, v[e]); }
    float s = 0.f;
#pragma unroll
    for (int e = 0; e < E_; e++) { v[e] = expf(v[e] - mx); s += v[e]; }
    float inv = 1.f / s;
#pragma unroll
    for (int e = 0; e < E_; e++) {
        float m = (masks[b * E_ + e] == 1) ? 1.f : 0.f;
        v[e] = v[e] * inv * m;
    }
    int i1 = 0;
#pragma unroll
    for (int e = 1; e < E_; e++) if (v[e] > v[i1]) i1 = e;
    int i2 = (i1 == 0) ? 1 : 0;
#pragma unroll
    for (int e = 0; e < E_; e++) if (e != i1 && v[e] > v[i2]) i2 = e;
    float g1 = v[i1], g2 = v[i2];
    float invs = 1.f / (g1 + g2 + 1e-9f);
    g_topk_idx[b] = make_int2(i1, i2);
    g_topk_w[b]   = make_float2(g1 * invs, g2 * invs);
}

// ---------------------------------------------------------------------------
// Kernel 0b: split x into bf16 hi/lo, zero-padded cols to FP=928
// ---------------------------------------------------------------------------
__global__ void split_x_kernel(const float* __restrict__ x) {
    int idx = blockIdx.x * 256 + threadIdx.x;
    if (idx >= NROWS * (FP / 8)) return;
    int row = idx / (FP / 8);
    int c8  = idx % (FP / 8);
    int f   = c8 * 8;
    const float* xr = x + (size_t)row * F_ + f;
    uint32_t hi[4], lo[4];
#pragma unroll
    for (int j = 0; j < 4; j++) {
        float v0 = (f + 2 * j     < F_) ? xr[2 * j]     : 0.f;
        float v1 = (f + 2 * j + 1 < F_) ? xr[2 * j + 1] : 0.f;
        split2(v0, v1, hi[j], lo[j]);
    }
    *(uint4*)(g_xhi + (size_t)row * FP + f) = make_uint4(hi[0], hi[1], hi[2], hi[3]);
    *(uint4*)(g_xlo + (size_t)row * FP + f) = make_uint4(lo[0], lo[1], lo[2], lo[3]);
}

// ---------------------------------------------------------------------------
// A prefetch (coalesced: item = tid + it*256).
// ---------------------------------------------------------------------------
__device__ __forceinline__ void issue_A(
    uint32_t stage_u,
    const __nv_bfloat16* __restrict__ xhi_b, const __nv_bfloat16* __restrict__ xlo_b,
    int k0, int tid) {
#pragma unroll
    for (int it = 0; it < 2; it++) {
        int i   = tid + it * 256;
        int row = i >> 2, q = i & 3;
        int rc  = (row < L_) ? row : 0;
        uint32_t sz = (row < L_) ? 16u : 0u;
        const __nv_bfloat16* sh = xhi_b + (size_t)rc * FP + k0 + q * 8;
        const __nv_bfloat16* sl = xlo_b + (size_t)rc * FP + k0 + q * 8;
        uint32_t off = swoff(row, q);
        cp16(stage_u + OFF_A_HI + off, sh, sz);
        cp16(stage_u + OFF_A_LO + off, sl, sz);
    }
}

// ---------------------------------------------------------------------------
// W producer (coalesced): direct LDG fp32, gate-mix, fast split, STS.
// ---------------------------------------------------------------------------
__device__ __forceinline__ void produce_W(
    char* __restrict__ stg,
    const float* __restrict__ W1, const float* __restrict__ W2,
    float gx, float gy, int k0, int tid) {
#pragma unroll
    for (int it = 0; it < 2; it++) {
        int item = tid + it * 256;
        int row  = item >> 2;
        int q    = item & 3;
        int f    = k0 + q * 8;
        float v[8] = {0.f, 0.f, 0.f, 0.f, 0.f, 0.f, 0.f, 0.f};
        if (f + 4 <= F_) {
            float4 a = *(const float4*)(W1 + (size_t)row * F_ + f);
            float4 c = *(const float4*)(W2 + (size_t)row * F_ + f);
            v[0] = fmaf(gx, a.x, gy * c.x); v[1] = fmaf(gx, a.y, gy * c.y);
            v[2] = fmaf(gx, a.z, gy * c.z); v[3] = fmaf(gx, a.w, gy * c.w);
        }
        if (f + 8 <= F_) {
            float4 a = *(const float4*)(W1 + (size_t)row * F_ + f + 4);
            float4 c = *(const float4*)(W2 + (size_t)row * F_ + f + 4);
            v[4] = fmaf(gx, a.x, gy * c.x); v[5] = fmaf(gx, a.y, gy * c.y);
            v[6] = fmaf(gx, a.z, gy * c.z); v[7] = fmaf(gx, a.w, gy * c.w);
        }
        uint32_t hi[4], lo[4];
#pragma unroll
        for (int j = 0; j < 4; j++)
            split2(v[2 * j], v[2 * j + 1], hi[j], lo[j]);
        uint32_t off = swoff(row, q);
        *(uint4*)(stg + OFF_B_HI + off) = make_uint4(hi[0], hi[1], hi[2], hi[3]);
        *(uint4*)(stg + OFF_B_LO + off) = make_uint4(lo[0], lo[1], lo[2], lo[3]);
    }
}

// ---------------------------------------------------------------------------
// Kernel 2: HMMA bf16 3-pass split GEMM; templated padding-skip per warp_m.
// ---------------------------------------------------------------------------
__global__ void __launch_bounds__(256, 2)
moe_hmma_kernel(const float* __restrict__ W,
                const float* __restrict__ bias,
                float* __restrict__ out) {
    extern __shared__ char smem[];
    const uint32_t sb = smem_u32(smem);
    float* bm = (float*)(smem + SM_BM);

    const int tid    = threadIdx.x;
    const int wid    = tid >> 5;
    const int lane   = tid & 31;
    const int warp_m = wid >> 2;
    const int warp_n = wid & 3;
    const int b      = blockIdx.y;
    const int dtile  = blockIdx.x;

    const int2   ei = g_topk_idx[b];
    const float2 gw = g_topk_w[b];

    const __nv_bfloat16* xhi_b = g_xhi + (size_t)b * L_ * FP;
    const __nv_bfloat16* xlo_b = g_xlo + (size_t)b * L_ * FP;
    const float* __restrict__ W1 = W + (size_t)ei.x * D_ * F_ + (size_t)dtile * BN * F_;
    const float* __restrict__ W2 = W + (size_t)ei.y * D_ * F_ + (size_t)dtile * BN * F_;

    if (tid < BN) {
        int d = dtile * BN + tid;
        bm[tid] = gw.x * bias[ei.x * D_ + d] + gw.y * bias[ei.y * D_ + d];
    }

    float acc[4][4][4];
#pragma unroll
    for (int mi = 0; mi < 4; mi++)
#pragma unroll
        for (int nj = 0; nj < 4; nj++)
#pragma unroll
            for (int q = 0; q < 4; q++) acc[mi][nj][q] = 0.f;

    // prologue: stage 0
    issue_A(sb + SM_STAGES, xhi_b, xlo_b, 0, tid);
    CP_COMMIT();
    produce_W(smem + SM_STAGES, W1, W2, gw.x, gw.y, 0, tid);
    CP_WAIT0();
    __syncthreads();

    const int arow0 = warp_m * 64 + (lane & 15);
    const int ahalf = lane >> 4;
    const int brow0 = warp_n * 32 + (lane & 7);
    const int bhalf = (lane >> 3) & 1;

    for (int t = 0; t < NKT; t++) {
        if (t + 1 < NKT) {
            issue_A(sb + SM_STAGES + ((t + 1) & 1) * STAGE_BYTES,
                    xhi_b, xlo_b, (t + 1) * BK, tid);
            CP_COMMIT();
        }

        const uint32_t aHiB = sb + SM_STAGES + (t & 1) * STAGE_BYTES + OFF_A_HI;
        const uint32_t aLoB = aHiB + (OFF_A_LO - OFF_A_HI);
        const uint32_t bHiB = aHiB + (OFF_B_HI - OFF_A_HI);
        const uint32_t bLoB = aHiB + (OFF_B_LO - OFF_A_HI);

        // warp_m==1's mi==3 fragment covers rows 112-127 (pure padding):
        // compile-time specialized skip, uniform per-warp branch.
        if (warp_m == 0)
            mma_steps<4>(acc, aHiB, aLoB, bHiB, bLoB, arow0, ahalf, brow0, bhalf);
        else
            mma_steps<3>(acc, aHiB, aLoB, bHiB, bLoB, arow0, ahalf, brow0, bhalf);

        if (t + 1 < NKT) {
            produce_W(smem + SM_STAGES + ((t + 1) & 1) * STAGE_BYTES,
                      W1, W2, gw.x, gw.y, (t + 1) * BK, tid);
            CP_WAIT0();
        }
        __syncthreads();
    }

    // ---- epilogue ----
    const int r_base = warp_m * 64 + (lane >> 2);
    const int c_base = warp_n * 32 + ((lane & 3) << 1);
#pragma unroll
    for (int mi = 0; mi < 4; mi++) {
#pragma unroll
        for (int half = 0; half < 2; half++) {
            int l = r_base + mi * 16 + half * 8;
            if (l >= L_) continue;
            float* orow = out + ((size_t)b * L_ + l) * D_ + dtile * BN;
#pragma unroll
            for (int nj = 0; nj < 4; nj++) {
                int c = c_base + nj * 8;
                float v0 = acc[mi][nj][half * 2 + 0] + bm[c];
                float v1 = acc[mi][nj][half * 2 + 1] + bm[c + 1];
                v0 = __bfloat162float(__float2bfloat16_rn(v0));
                v1 = __bfloat162float(__float2bfloat16_rn(v1));
                *(float2*)(orow + c) = make_float2(v0, v1);
            }
        }
    }
}

// ---------------------------------------------------------------------------
extern "C" void kernel_launch(void* const* d_in, const int* in_sizes, int n_in,
                              void* d_out, int out_size) {
    const void* x_p = nullptr;
    const void* W_p = nullptr;
    const void* b_p = nullptr;
    const void* c1024[2] = {nullptr, nullptr};
    int n1024 = 0;

    for (int i = 0; i < n_in; i++) {
        switch (in_sizes[i]) {
            case 11520000: x_p = d_in[i]; break;
            case 3686400:  W_p = d_in[i]; break;
            case 4096:     b_p = d_in[i]; break;
            case 1024: if (n1024 < 2) c1024[n1024++] = d_in[i]; break;
            default: break;
        }
    }
    if (!x_p || !W_p || !b_p || n1024 != 2) {
        x_p = d_in[0]; c1024[0] = d_in[1]; c1024[1] = d_in[2];
        W_p = d_in[3]; b_p = d_in[4];
    }

    float* out = (float*)d_out;

    cudaFuncSetAttribute(moe_hmma_kernel,
                         cudaFuncAttributeMaxDynamicSharedMemorySize, SMEM_TOTAL);

    gates_kernel<<<1, B_>>>(c1024[0], c1024[1]);
    split_x_kernel<<<(NROWS * (FP / 8) + 255) / 256, 256>>>((const float*)x_p);

    dim3 grid(D_ / BN, B_);   // (4, 128)
    moe_hmma_kernel<<<grid, 256, SMEM_TOTAL>>>((const float*)W_p,
                                               (const float*)b_p, out);
}

// round 15
// speedup vs baseline: 1.3714x; 1.0028x over previous
#include <cuda_runtime.h>
#include <cuda_bf16.h>
#include <stdint.h>

// Problem constants
#define B_   128
#define L_   100
#define F_   900
#define D_   512
#define E_   8

#define BN   128
#define BK   32
#define NKT  29      // ceil(900/32), padded to 928
#define FP   928
#define NROWS (B_ * L_)

// Shared memory layout
#define SM_BM     0
#define SM_STAGES 1024
#define STAGE_BYTES 32768
#define OFF_A_HI  0
#define OFF_A_LO  8192
#define OFF_B_HI  16384
#define OFF_B_LO  24576
#define SMEM_TOTAL (SM_STAGES + 2 * STAGE_BYTES)   // 66560 -> 2 CTAs/SM

// Global scratch
__device__ __nv_bfloat16 g_xhi[(size_t)NROWS * FP];
__device__ __nv_bfloat16 g_xlo[(size_t)NROWS * FP];

// ---------------- helpers ----------------
__device__ __forceinline__ uint32_t smem_u32(const void* p) {
    uint32_t a;
    asm("{ .reg .u64 t; cvta.to.shared.u64 t, %1; cvt.u32.u64 %0, t; }" : "=r"(a) : "l"(p));
    return a;
}
__device__ __forceinline__ uint32_t swoff(int row, int q) {
    return (uint32_t)(row * 64) + (uint32_t)((q ^ ((row >> 1) & 3)) << 4);
}
__device__ __forceinline__ void cp16(uint32_t dst, const void* src, uint32_t sz) {
    asm volatile("cp.async.cg.shared.global [%0], [%1], 16, %2;"
                 :: "r"(dst), "l"(src), "r"(sz) : "memory");
}
#define CP_COMMIT() asm volatile("cp.async.commit_group;" ::: "memory")
#define CP_WAIT0()  asm volatile("cp.async.wait_group 0;" ::: "memory")

#define LDSM4(r, addr) \
    asm volatile("ldmatrix.sync.aligned.m8n8.x4.shared.b16 {%0,%1,%2,%3}, [%4];" \
        : "=r"((r)[0]), "=r"((r)[1]), "=r"((r)[2]), "=r"((r)[3]) : "r"(addr))
#define LDSM2(r, addr) \
    asm volatile("ldmatrix.sync.aligned.m8n8.x2.shared.b16 {%0,%1}, [%2];" \
        : "=r"((r)[0]), "=r"((r)[1]) : "r"(addr))
#define MMA16816(c, a, bb) \
    asm volatile("mma.sync.aligned.m16n8k16.row.col.f32.bf16.bf16.f32 " \
        "{%0,%1,%2,%3}, {%4,%5,%6,%7}, {%8,%9}, {%0,%1,%2,%3};" \
        : "+f"((c)[0]), "+f"((c)[1]), "+f"((c)[2]), "+f"((c)[3]) \
        : "r"((a)[0]), "r"((a)[1]), "r"((a)[2]), "r"((a)[3]), "r"((bb)[0]), "r"((bb)[1]))

// Fast bf16 hi/lo split: bit-identical to per-element rn split.
__device__ __forceinline__ void split2(float v0, float v1, uint32_t& hp, uint32_t& lp) {
    asm("cvt.rn.bf16x2.f32 %0, %1, %2;" : "=r"(hp) : "f"(v1), "f"(v0));
    float f0h = __uint_as_float(hp << 16);
    float f1h = __uint_as_float(hp & 0xFFFF0000u);
    float l0 = v0 - f0h;
    float l1 = v1 - f1h;
    asm("cvt.rn.bf16x2.f32 %0, %1, %2;" : "=r"(lp) : "f"(l1), "f"(l0));
}

// Inline gating for one sample (identical arithmetic to the old gates_kernel).
__device__ __forceinline__ void compute_gates(
    const void* __restrict__ candA, const void* __restrict__ candB, int b,
    int2& ei, float2& gwv) {
    const int* ai = (const int*)candA;
    bool aIsMask = true;
#pragma unroll
    for (int e = 0; e < E_; e++) {
        int t = ai[b * E_ + e];
        if (t != 0 && t != 1) aIsMask = false;
    }
    const float* logits = aIsMask ? (const float*)candB : (const float*)candA;
    const int*   masks  = aIsMask ? (const int*)candA   : (const int*)candB;

    float v[E_]; float mx = -1e30f;
#pragma unroll
    for (int e = 0; e < E_; e++) { v[e] = logits[b * E_ + e]; mx = fmaxf(mx, v[e]); }
    float s = 0.f;
#pragma unroll
    for (int e = 0; e < E_; e++) { v[e] = expf(v[e] - mx); s += v[e]; }
    float inv = 1.f / s;
#pragma unroll
    for (int e = 0; e < E_; e++) {
        float m = (masks[b * E_ + e] == 1) ? 1.f : 0.f;
        v[e] = v[e] * inv * m;
    }
    int i1 = 0;
#pragma unroll
    for (int e = 1; e < E_; e++) if (v[e] > v[i1]) i1 = e;
    int i2 = (i1 == 0) ? 1 : 0;
#pragma unroll
    for (int e = 0; e < E_; e++) if (e != i1 && v[e] > v[i2]) i2 = e;
    float g1 = v[i1], g2 = v[i2];
    float invs = 1.f / (g1 + g2 + 1e-9f);
    ei  = make_int2(i1, i2);
    gwv = make_float2(g1 * invs, g2 * invs);
}

// ---------------------------------------------------------------------------
// Templated per-ktile MMA body: MI = valid M fragments (4 for warp_m 0,
// 3 for warp_m 1 -- its mi==3 covers rows 112..127, pure L-padding).
// ---------------------------------------------------------------------------
template<int MI>
__device__ __forceinline__ void mma_steps(
    float (&acc)[4][4][4],
    uint32_t aHiB, uint32_t aLoB, uint32_t bHiB, uint32_t bLoB,
    int arow0, int ahalf, int brow0, int bhalf) {
#pragma unroll
    for (int s = 0; s < 2; s++) {
        const int aq = 2 * s + ahalf;
        const int bq = 2 * s + bhalf;
        uint32_t aX[MI][4];

        // pass A-hi: hi*hi + hi*lo
#pragma unroll
        for (int mi = 0; mi < MI; mi++)
            LDSM4(aX[mi], aHiB + swoff(arow0 + mi * 16, aq));
#pragma unroll
        for (int nj = 0; nj < 4; nj++) {
            uint32_t bh[2], bl[2];
            uint32_t boff = swoff(brow0 + nj * 8, bq);
            LDSM2(bh, bHiB + boff);
            LDSM2(bl, bLoB + boff);
#pragma unroll
            for (int mi = 0; mi < MI; mi++) {
                MMA16816(acc[mi][nj], aX[mi], bh);
                MMA16816(acc[mi][nj], aX[mi], bl);
            }
        }
        // pass A-lo: lo*hi
#pragma unroll
        for (int mi = 0; mi < MI; mi++)
            LDSM4(aX[mi], aLoB + swoff(arow0 + mi * 16, aq));
#pragma unroll
        for (int nj = 0; nj < 4; nj++) {
            uint32_t bh[2];
            LDSM2(bh, bHiB + swoff(brow0 + nj * 8, bq));
#pragma unroll
            for (int mi = 0; mi < MI; mi++)
                MMA16816(acc[mi][nj], aX[mi], bh);
        }
    }
}

// ---------------------------------------------------------------------------
// Kernel 0: split x into bf16 hi/lo, zero-padded cols to FP=928
// ---------------------------------------------------------------------------
__global__ void split_x_kernel(const float* __restrict__ x) {
    int idx = blockIdx.x * 256 + threadIdx.x;
    if (idx >= NROWS * (FP / 8)) return;
    int row = idx / (FP / 8);
    int c8  = idx % (FP / 8);
    int f   = c8 * 8;
    const float* xr = x + (size_t)row * F_ + f;
    uint32_t hi[4], lo[4];
#pragma unroll
    for (int j = 0; j < 4; j++) {
        float v0 = (f + 2 * j     < F_) ? xr[2 * j]     : 0.f;
        float v1 = (f + 2 * j + 1 < F_) ? xr[2 * j + 1] : 0.f;
        split2(v0, v1, hi[j], lo[j]);
    }
    *(uint4*)(g_xhi + (size_t)row * FP + f) = make_uint4(hi[0], hi[1], hi[2], hi[3]);
    *(uint4*)(g_xlo + (size_t)row * FP + f) = make_uint4(lo[0], lo[1], lo[2], lo[3]);
}

// ---------------------------------------------------------------------------
// A prefetch (coalesced: item = tid + it*256).
// ---------------------------------------------------------------------------
__device__ __forceinline__ void issue_A(
    uint32_t stage_u,
    const __nv_bfloat16* __restrict__ xhi_b, const __nv_bfloat16* __restrict__ xlo_b,
    int k0, int tid) {
#pragma unroll
    for (int it = 0; it < 2; it++) {
        int i   = tid + it * 256;
        int row = i >> 2, q = i & 3;
        int rc  = (row < L_) ? row : 0;
        uint32_t sz = (row < L_) ? 16u : 0u;
        const __nv_bfloat16* sh = xhi_b + (size_t)rc * FP + k0 + q * 8;
        const __nv_bfloat16* sl = xlo_b + (size_t)rc * FP + k0 + q * 8;
        uint32_t off = swoff(row, q);
        cp16(stage_u + OFF_A_HI + off, sh, sz);
        cp16(stage_u + OFF_A_LO + off, sl, sz);
    }
}

// ---------------------------------------------------------------------------
// W producer (coalesced): direct LDG fp32, gate-mix, fast split, STS.
// ---------------------------------------------------------------------------
__device__ __forceinline__ void produce_W(
    char* __restrict__ stg,
    const float* __restrict__ W1, const float* __restrict__ W2,
    float gx, float gy, int k0, int tid) {
#pragma unroll
    for (int it = 0; it < 2; it++) {
        int item = tid + it * 256;
        int row  = item >> 2;
        int q    = item & 3;
        int f    = k0 + q * 8;
        float v[8] = {0.f, 0.f, 0.f, 0.f, 0.f, 0.f, 0.f, 0.f};
        if (f + 4 <= F_) {
            float4 a = *(const float4*)(W1 + (size_t)row * F_ + f);
            float4 c = *(const float4*)(W2 + (size_t)row * F_ + f);
            v[0] = fmaf(gx, a.x, gy * c.x); v[1] = fmaf(gx, a.y, gy * c.y);
            v[2] = fmaf(gx, a.z, gy * c.z); v[3] = fmaf(gx, a.w, gy * c.w);
        }
        if (f + 8 <= F_) {
            float4 a = *(const float4*)(W1 + (size_t)row * F_ + f + 4);
            float4 c = *(const float4*)(W2 + (size_t)row * F_ + f + 4);
            v[4] = fmaf(gx, a.x, gy * c.x); v[5] = fmaf(gx, a.y, gy * c.y);
            v[6] = fmaf(gx, a.z, gy * c.z); v[7] = fmaf(gx, a.w, gy * c.w);
        }
        uint32_t hi[4], lo[4];
#pragma unroll
        for (int j = 0; j < 4; j++)
            split2(v[2 * j], v[2 * j + 1], hi[j], lo[j]);
        uint32_t off = swoff(row, q);
        *(uint4*)(stg + OFF_B_HI + off) = make_uint4(hi[0], hi[1], hi[2], hi[3]);
        *(uint4*)(stg + OFF_B_LO + off) = make_uint4(lo[0], lo[1], lo[2], lo[3]);
    }
}

// ---------------------------------------------------------------------------
// Kernel 1: HMMA bf16 3-pass split GEMM; inline gating; templated MI skip.
// ---------------------------------------------------------------------------
__global__ void __launch_bounds__(256, 2)
moe_hmma_kernel(const float* __restrict__ W,
                const float* __restrict__ bias,
                const void* __restrict__ candA,
                const void* __restrict__ candB,
                float* __restrict__ out) {
    extern __shared__ char smem[];
    const uint32_t sb = smem_u32(smem);
    float* bm = (float*)(smem + SM_BM);

    const int tid    = threadIdx.x;
    const int wid    = tid >> 5;
    const int lane   = tid & 31;
    const int warp_m = wid >> 2;
    const int warp_n = wid & 3;
    const int b      = blockIdx.y;
    const int dtile  = blockIdx.x;

    // Inline gating (redundant per block; hidden behind prologue).
    int2 ei; float2 gw;
    compute_gates(candA, candB, b, ei, gw);

    const __nv_bfloat16* xhi_b = g_xhi + (size_t)b * L_ * FP;
    const __nv_bfloat16* xlo_b = g_xlo + (size_t)b * L_ * FP;
    const float* __restrict__ W1 = W + (size_t)ei.x * D_ * F_ + (size_t)dtile * BN * F_;
    const float* __restrict__ W2 = W + (size_t)ei.y * D_ * F_ + (size_t)dtile * BN * F_;

    if (tid < BN) {
        int d = dtile * BN + tid;
        bm[tid] = gw.x * bias[ei.x * D_ + d] + gw.y * bias[ei.y * D_ + d];
    }

    float acc[4][4][4];
#pragma unroll
    for (int mi = 0; mi < 4; mi++)
#pragma unroll
        for (int nj = 0; nj < 4; nj++)
#pragma unroll
            for (int q = 0; q < 4; q++) acc[mi][nj][q] = 0.f;

    // prologue: stage 0
    issue_A(sb + SM_STAGES, xhi_b, xlo_b, 0, tid);
    CP_COMMIT();
    produce_W(smem + SM_STAGES, W1, W2, gw.x, gw.y, 0, tid);
    CP_WAIT0();
    __syncthreads();

    const int arow0 = warp_m * 64 + (lane & 15);
    const int ahalf = lane >> 4;
    const int brow0 = warp_n * 32 + (lane & 7);
    const int bhalf = (lane >> 3) & 1;

    for (int t = 0; t < NKT; t++) {
        if (t + 1 < NKT) {
            issue_A(sb + SM_STAGES + ((t + 1) & 1) * STAGE_BYTES,
                    xhi_b, xlo_b, (t + 1) * BK, tid);
            CP_COMMIT();
        }

        const uint32_t aHiB = sb + SM_STAGES + (t & 1) * STAGE_BYTES + OFF_A_HI;
        const uint32_t aLoB = aHiB + (OFF_A_LO - OFF_A_HI);
        const uint32_t bHiB = aHiB + (OFF_B_HI - OFF_A_HI);
        const uint32_t bLoB = aHiB + (OFF_B_LO - OFF_A_HI);

        if (warp_m == 0)
            mma_steps<4>(acc, aHiB, aLoB, bHiB, bLoB, arow0, ahalf, brow0, bhalf);
        else
            mma_steps<3>(acc, aHiB, aLoB, bHiB, bLoB, arow0, ahalf, brow0, bhalf);

        if (t + 1 < NKT) {
            produce_W(smem + SM_STAGES + ((t + 1) & 1) * STAGE_BYTES,
                      W1, W2, gw.x, gw.y, (t + 1) * BK, tid);
            CP_WAIT0();
        }
        __syncthreads();
    }

    // ---- epilogue ----
    const int r_base = warp_m * 64 + (lane >> 2);
    const int c_base = warp_n * 32 + ((lane & 3) << 1);
#pragma unroll
    for (int mi = 0; mi < 4; mi++) {
#pragma unroll
        for (int half = 0; half < 2; half++) {
            int l = r_base + mi * 16 + half * 8;
            if (l >= L_) continue;
            float* orow = out + ((size_t)b * L_ + l) * D_ + dtile * BN;
#pragma unroll
            for (int nj = 0; nj < 4; nj++) {
                int c = c_base + nj * 8;
                float v0 = acc[mi][nj][half * 2 + 0] + bm[c];
                float v1 = acc[mi][nj][half * 2 + 1] + bm[c + 1];
                v0 = __bfloat162float(__float2bfloat16_rn(v0));
                v1 = __bfloat162float(__float2bfloat16_rn(v1));
                *(float2*)(orow + c) = make_float2(v0, v1);
            }
        }
    }
}

// ---------------------------------------------------------------------------
extern "C" void kernel_launch(void* const* d_in, const int* in_sizes, int n_in,
                              void* d_out, int out_size) {
    const void* x_p = nullptr;
    const void* W_p = nullptr;
    const void* b_p = nullptr;
    const void* c1024[2] = {nullptr, nullptr};
    int n1024 = 0;

    for (int i = 0; i < n_in; i++) {
        switch (in_sizes[i]) {
            case 11520000: x_p = d_in[i]; break;
            case 3686400:  W_p = d_in[i]; break;
            case 4096:     b_p = d_in[i]; break;
            case 1024: if (n1024 < 2) c1024[n1024++] = d_in[i]; break;
            default: break;
        }
    }
    if (!x_p || !W_p || !b_p || n1024 != 2) {
        x_p = d_in[0]; c1024[0] = d_in[1]; c1024[1] = d_in[2];
        W_p = d_in[3]; b_p = d_in[4];
    }

    float* out = (float*)d_out;

    cudaFuncSetAttribute(moe_hmma_kernel,
                         cudaFuncAttributeMaxDynamicSharedMemorySize, SMEM_TOTAL);

    split_x_kernel<<<(NROWS * (FP / 8) + 255) / 256, 256>>>((const float*)x_p);

    dim3 grid(D_ / BN, B_);   // (4, 128)
    moe_hmma_kernel<<<grid, 256, SMEM_TOTAL>>>((const float*)W_p,
                                               (const float*)b_p,
                                               c1024[0], c1024[1], out);
}

// round 16
// speedup vs baseline: 1.4456x; 1.0542x over previous
#include <cuda_runtime.h>
#include <cuda_bf16.h>
#include <stdint.h>

// Problem constants
#define B_   128
#define L_   100
#define F_   900
#define D_   512
#define E_   8

#define BN   128
#define BK   32
#define NKT  29      // ceil(900/32), padded to 928
#define FP   928
#define NROWS (B_ * L_)

// Shared memory layout
#define SM_BM     0
#define SM_STAGES 1024
#define STAGE_BYTES 32768
#define OFF_A_HI  0
#define OFF_A_LO  8192
#define OFF_B_HI  16384
#define OFF_B_LO  24576
#define SMEM_TOTAL (SM_STAGES + 2 * STAGE_BYTES)   // 66560 -> 2 CTAs/SM

// Global scratch
__device__ __nv_bfloat16 g_xhi[(size_t)NROWS * FP];
__device__ __nv_bfloat16 g_xlo[(size_t)NROWS * FP];

// ---------------- helpers ----------------
__device__ __forceinline__ uint32_t smem_u32(const void* p) {
    uint32_t a;
    asm("{ .reg .u64 t; cvta.to.shared.u64 t, %1; cvt.u32.u64 %0, t; }" : "=r"(a) : "l"(p));
    return a;
}
__device__ __forceinline__ uint32_t swoff(int row, int q) {
    return (uint32_t)(row * 64) + (uint32_t)((q ^ ((row >> 1) & 3)) << 4);
}
__device__ __forceinline__ void cp16(uint32_t dst, const void* src, uint32_t sz) {
    asm volatile("cp.async.cg.shared.global [%0], [%1], 16, %2;"
                 :: "r"(dst), "l"(src), "r"(sz) : "memory");
}
#define CP_COMMIT() asm volatile("cp.async.commit_group;" ::: "memory")
#define CP_WAIT0()  asm volatile("cp.async.wait_group 0;" ::: "memory")

#define LDSM4(r, addr) \
    asm volatile("ldmatrix.sync.aligned.m8n8.x4.shared.b16 {%0,%1,%2,%3}, [%4];" \
        : "=r"((r)[0]), "=r"((r)[1]), "=r"((r)[2]), "=r"((r)[3]) : "r"(addr))
#define LDSM2(r, addr) \
    asm volatile("ldmatrix.sync.aligned.m8n8.x2.shared.b16 {%0,%1}, [%2];" \
        : "=r"((r)[0]), "=r"((r)[1]) : "r"(addr))
#define MMA16816(c, a, bb) \
    asm volatile("mma.sync.aligned.m16n8k16.row.col.f32.bf16.bf16.f32 " \
        "{%0,%1,%2,%3}, {%4,%5,%6,%7}, {%8,%9}, {%0,%1,%2,%3};" \
        : "+f"((c)[0]), "+f"((c)[1]), "+f"((c)[2]), "+f"((c)[3]) \
        : "r"((a)[0]), "r"((a)[1]), "r"((a)[2]), "r"((a)[3]), "r"((bb)[0]), "r"((bb)[1]))

// Fast bf16 hi/lo split: bit-identical to per-element rn split.
__device__ __forceinline__ void split2(float v0, float v1, uint32_t& hp, uint32_t& lp) {
    asm("cvt.rn.bf16x2.f32 %0, %1, %2;" : "=r"(hp) : "f"(v1), "f"(v0));
    float f0h = __uint_as_float(hp << 16);
    float f1h = __uint_as_float(hp & 0xFFFF0000u);
    float l0 = v0 - f0h;
    float l1 = v1 - f1h;
    asm("cvt.rn.bf16x2.f32 %0, %1, %2;" : "=r"(lp) : "f"(l1), "f"(l0));
}

// Inline gating for one sample.
__device__ __forceinline__ void compute_gates(
    const void* __restrict__ candA, const void* __restrict__ candB, int b,
    int2& ei, float2& gwv) {
    const int* ai = (const int*)candA;
    bool aIsMask = true;
#pragma unroll
    for (int e = 0; e < E_; e++) {
        int t = ai[b * E_ + e];
        if (t != 0 && t != 1) aIsMask = false;
    }
    const float* logits = aIsMask ? (const float*)candB : (const float*)candA;
    const int*   masks  = aIsMask ? (const int*)candA   : (const int*)candB;

    float v[E_]; float mx = -1e30f;
#pragma unroll
    for (int e = 0; e < E_; e++) { v[e] = logits[b * E_ + e]; mx = fmaxf(mx, v[e]); }
    float s = 0.f;
#pragma unroll
    for (int e = 0; e < E_; e++) { v[e] = expf(v[e] - mx); s += v[e]; }
    float inv = 1.f / s;
#pragma unroll
    for (int e = 0; e < E_; e++) {
        float m = (masks[b * E_ + e] == 1) ? 1.f : 0.f;
        v[e] = v[e] * inv * m;
    }
    int i1 = 0;
#pragma unroll
    for (int e = 1; e < E_; e++) if (v[e] > v[i1]) i1 = e;
    int i2 = (i1 == 0) ? 1 : 0;
#pragma unroll
    for (int e = 0; e < E_; e++) if (e != i1 && v[e] > v[i2]) i2 = e;
    float g1 = v[i1], g2 = v[i2];
    float invs = 1.f / (g1 + g2 + 1e-9f);
    ei  = make_int2(i1, i2);
    gwv = make_float2(g1 * invs, g2 * invs);
}

// ---------------------------------------------------------------------------
// Templated per-ktile MMA body, B-fragment-reuse order:
//   per s: load all B fragments once (8 LDSM2), then per mi load aHi/aLo and
//   run the 3 passes. Same per-accumulator add order -> bit-identical.
// MI = valid M fragments (4 for warp_m 0, 3 for warp_m 1; its mi==3 covers
// rows 112..127 = pure L-padding).
// ---------------------------------------------------------------------------
template<int MI>
__device__ __forceinline__ void mma_steps(
    float (&acc)[4][4][4],
    uint32_t aHiB, uint32_t aLoB, uint32_t bHiB, uint32_t bLoB,
    int arow0, int ahalf, int brow0, int bhalf) {
#pragma unroll
    for (int s = 0; s < 2; s++) {
        const int aq = 2 * s + ahalf;
        const int bq = 2 * s + bhalf;

        // Load all B fragments once for this k16 substep.
        uint32_t bh[4][2], bl[4][2];
#pragma unroll
        for (int nj = 0; nj < 4; nj++) {
            uint32_t boff = swoff(brow0 + nj * 8, bq);
            LDSM2(bh[nj], bHiB + boff);
            LDSM2(bl[nj], bLoB + boff);
        }

#pragma unroll
        for (int mi = 0; mi < MI; mi++) {
            uint32_t aH[4], aL[4];
            LDSM4(aH, aHiB + swoff(arow0 + mi * 16, aq));
            // hi*hi then hi*lo (same per-acc order as before)
#pragma unroll
            for (int nj = 0; nj < 4; nj++) {
                MMA16816(acc[mi][nj], aH, bh[nj]);
                MMA16816(acc[mi][nj], aH, bl[nj]);
            }
            LDSM4(aL, aLoB + swoff(arow0 + mi * 16, aq));
            // lo*hi
#pragma unroll
            for (int nj = 0; nj < 4; nj++)
                MMA16816(acc[mi][nj], aL, bh[nj]);
        }
    }
}

// ---------------------------------------------------------------------------
// Kernel 0: split x into bf16 hi/lo, zero-padded cols to FP=928
// ---------------------------------------------------------------------------
__global__ void split_x_kernel(const float* __restrict__ x) {
    int idx = blockIdx.x * 256 + threadIdx.x;
    if (idx >= NROWS * (FP / 8)) return;
    int row = idx / (FP / 8);
    int c8  = idx % (FP / 8);
    int f   = c8 * 8;
    const float* xr = x + (size_t)row * F_ + f;
    uint32_t hi[4], lo[4];
#pragma unroll
    for (int j = 0; j < 4; j++) {
        float v0 = (f + 2 * j     < F_) ? xr[2 * j]     : 0.f;
        float v1 = (f + 2 * j + 1 < F_) ? xr[2 * j + 1] : 0.f;
        split2(v0, v1, hi[j], lo[j]);
    }
    *(uint4*)(g_xhi + (size_t)row * FP + f) = make_uint4(hi[0], hi[1], hi[2], hi[3]);
    *(uint4*)(g_xlo + (size_t)row * FP + f) = make_uint4(lo[0], lo[1], lo[2], lo[3]);
}

// ---------------------------------------------------------------------------
// A prefetch (coalesced: item = tid + it*256).
// ---------------------------------------------------------------------------
__device__ __forceinline__ void issue_A(
    uint32_t stage_u,
    const __nv_bfloat16* __restrict__ xhi_b, const __nv_bfloat16* __restrict__ xlo_b,
    int k0, int tid) {
#pragma unroll
    for (int it = 0; it < 2; it++) {
        int i   = tid + it * 256;
        int row = i >> 2, q = i & 3;
        int rc  = (row < L_) ? row : 0;
        uint32_t sz = (row < L_) ? 16u : 0u;
        const __nv_bfloat16* sh = xhi_b + (size_t)rc * FP + k0 + q * 8;
        const __nv_bfloat16* sl = xlo_b + (size_t)rc * FP + k0 + q * 8;
        uint32_t off = swoff(row, q);
        cp16(stage_u + OFF_A_HI + off, sh, sz);
        cp16(stage_u + OFF_A_LO + off, sl, sz);
    }
}

// ---------------------------------------------------------------------------
// W producer (coalesced): direct LDG fp32, gate-mix, fast split, STS.
// ---------------------------------------------------------------------------
__device__ __forceinline__ void produce_W(
    char* __restrict__ stg,
    const float* __restrict__ W1, const float* __restrict__ W2,
    float gx, float gy, int k0, int tid) {
#pragma unroll
    for (int it = 0; it < 2; it++) {
        int item = tid + it * 256;
        int row  = item >> 2;
        int q    = item & 3;
        int f    = k0 + q * 8;
        float v[8] = {0.f, 0.f, 0.f, 0.f, 0.f, 0.f, 0.f, 0.f};
        if (f + 4 <= F_) {
            float4 a = *(const float4*)(W1 + (size_t)row * F_ + f);
            float4 c = *(const float4*)(W2 + (size_t)row * F_ + f);
            v[0] = fmaf(gx, a.x, gy * c.x); v[1] = fmaf(gx, a.y, gy * c.y);
            v[2] = fmaf(gx, a.z, gy * c.z); v[3] = fmaf(gx, a.w, gy * c.w);
        }
        if (f + 8 <= F_) {
            float4 a = *(const float4*)(W1 + (size_t)row * F_ + f + 4);
            float4 c = *(const float4*)(W2 + (size_t)row * F_ + f + 4);
            v[4] = fmaf(gx, a.x, gy * c.x); v[5] = fmaf(gx, a.y, gy * c.y);
            v[6] = fmaf(gx, a.z, gy * c.z); v[7] = fmaf(gx, a.w, gy * c.w);
        }
        uint32_t hi[4], lo[4];
#pragma unroll
        for (int j = 0; j < 4; j++)
            split2(v[2 * j], v[2 * j + 1], hi[j], lo[j]);
        uint32_t off = swoff(row, q);
        *(uint4*)(stg + OFF_B_HI + off) = make_uint4(hi[0], hi[1], hi[2], hi[3]);
        *(uint4*)(stg + OFF_B_LO + off) = make_uint4(lo[0], lo[1], lo[2], lo[3]);
    }
}

// ---------------------------------------------------------------------------
// Kernel 1: HMMA bf16 3-pass split GEMM; inline gating; templated MI skip.
// ---------------------------------------------------------------------------
__global__ void __launch_bounds__(256, 2)
moe_hmma_kernel(const float* __restrict__ W,
                const float* __restrict__ bias,
                const void* __restrict__ candA,
                const void* __restrict__ candB,
                float* __restrict__ out) {
    extern __shared__ char smem[];
    const uint32_t sb = smem_u32(smem);
    float* bm = (float*)(smem + SM_BM);

    const int tid    = threadIdx.x;
    const int wid    = tid >> 5;
    const int lane   = tid & 31;
    const int warp_m = wid >> 2;
    const int warp_n = wid & 3;
    const int b      = blockIdx.y;
    const int dtile  = blockIdx.x;

    int2 ei; float2 gw;
    compute_gates(candA, candB, b, ei, gw);

    const __nv_bfloat16* xhi_b = g_xhi + (size_t)b * L_ * FP;
    const __nv_bfloat16* xlo_b = g_xlo + (size_t)b * L_ * FP;
    const float* __restrict__ W1 = W + (size_t)ei.x * D_ * F_ + (size_t)dtile * BN * F_;
    const float* __restrict__ W2 = W + (size_t)ei.y * D_ * F_ + (size_t)dtile * BN * F_;

    if (tid < BN) {
        int d = dtile * BN + tid;
        bm[tid] = gw.x * bias[ei.x * D_ + d] + gw.y * bias[ei.y * D_ + d];
    }

    float acc[4][4][4];
#pragma unroll
    for (int mi = 0; mi < 4; mi++)
#pragma unroll
        for (int nj = 0; nj < 4; nj++)
#pragma unroll
            for (int q = 0; q < 4; q++) acc[mi][nj][q] = 0.f;

    // prologue: stage 0
    issue_A(sb + SM_STAGES, xhi_b, xlo_b, 0, tid);
    CP_COMMIT();
    produce_W(smem + SM_STAGES, W1, W2, gw.x, gw.y, 0, tid);
    CP_WAIT0();
    __syncthreads();

    const int arow0 = warp_m * 64 + (lane & 15);
    const int ahalf = lane >> 4;
    const int brow0 = warp_n * 32 + (lane & 7);
    const int bhalf = (lane >> 3) & 1;

    for (int t = 0; t < NKT; t++) {
        if (t + 1 < NKT) {
            issue_A(sb + SM_STAGES + ((t + 1) & 1) * STAGE_BYTES,
                    xhi_b, xlo_b, (t + 1) * BK, tid);
            CP_COMMIT();
        }

        const uint32_t aHiB = sb + SM_STAGES + (t & 1) * STAGE_BYTES + OFF_A_HI;
        const uint32_t aLoB = aHiB + (OFF_A_LO - OFF_A_HI);
        const uint32_t bHiB = aHiB + (OFF_B_HI - OFF_A_HI);
        const uint32_t bLoB = aHiB + (OFF_B_LO - OFF_A_HI);

        if (warp_m == 0)
            mma_steps<4>(acc, aHiB, aLoB, bHiB, bLoB, arow0, ahalf, brow0, bhalf);
        else
            mma_steps<3>(acc, aHiB, aLoB, bHiB, bLoB, arow0, ahalf, brow0, bhalf);

        if (t + 1 < NKT) {
            produce_W(smem + SM_STAGES + ((t + 1) & 1) * STAGE_BYTES,
                      W1, W2, gw.x, gw.y, (t + 1) * BK, tid);
            CP_WAIT0();
        }
        __syncthreads();
    }

    // ---- epilogue ----
    const int r_base = warp_m * 64 + (lane >> 2);
    const int c_base = warp_n * 32 + ((lane & 3) << 1);
#pragma unroll
    for (int mi = 0; mi < 4; mi++) {
#pragma unroll
        for (int half = 0; half < 2; half++) {
            int l = r_base + mi * 16 + half * 8;
            if (l >= L_) continue;
            float* orow = out + ((size_t)b * L_ + l) * D_ + dtile * BN;
#pragma unroll
            for (int nj = 0; nj < 4; nj++) {
                int c = c_base + nj * 8;
                float v0 = acc[mi][nj][half * 2 + 0] + bm[c];
                float v1 = acc[mi][nj][half * 2 + 1] + bm[c + 1];
                v0 = __bfloat162float(__float2bfloat16_rn(v0));
                v1 = __bfloat162float(__float2bfloat16_rn(v1));
                *(float2*)(orow + c) = make_float2(v0, v1);
            }
        }
    }
}

// ---------------------------------------------------------------------------
extern "C" void kernel_launch(void* const* d_in, const int* in_sizes, int n_in,
                              void* d_out, int out_size) {
    const void* x_p = nullptr;
    const void* W_p = nullptr;
    const void* b_p = nullptr;
    const void* c1024[2] = {nullptr, nullptr};
    int n1024 = 0;

    for (int i = 0; i < n_in; i++) {
        switch (in_sizes[i]) {
            case 11520000: x_p = d_in[i]; break;
            case 3686400:  W_p = d_in[i]; break;
            case 4096:     b_p = d_in[i]; break;
            case 1024: if (n1024 < 2) c1024[n1024++] = d_in[i]; break;
            default: break;
        }
    }
    if (!x_p || !W_p || !b_p || n1024 != 2) {
        x_p = d_in[0]; c1024[0] = d_in[1]; c1024[1] = d_in[2];
        W_p = d_in[3]; b_p = d_in[4];
    }

    float* out = (float*)d_out;

    cudaFuncSetAttribute(moe_hmma_kernel,
                         cudaFuncAttributeMaxDynamicSharedMemorySize, SMEM_TOTAL);

    split_x_kernel<<<(NROWS * (FP / 8) + 255) / 256, 256>>>((const float*)x_p);

    dim3 grid(D_ / BN, B_);   // (4, 128)
    moe_hmma_kernel<<<grid, 256, SMEM_TOTAL>>>((const float*)W_p,
                                               (const float*)b_p,
                                               c1024[0], c1024[1], out);
}